// round 15
// baseline (speedup 1.0000x reference)
#include <cuda_runtime.h>
#include <cuda_fp16.h>
#include <cstdint>

#define N_NODES 100000
#define N_EDGES 600000
#define N_GRAPHS 5000
#define IN_DIM 11
#define HID 128
#define EDGE_DIM 3
#define N_REST 4
#define BN_EPS 1e-5f

// ======================= PTX helpers (baseline sm_80+ ISA only) =======================
__device__ __forceinline__ uint32_t smem_u32(const void* p) {
    uint32_t a;
    asm("{ .reg .u64 t; cvta.to.shared.u64 t, %1; cvt.u32.u64 %0, t; }" : "=r"(a) : "l"(p));
    return a;
}

#define LDSM_X4(r0, r1, r2, r3, addr)                                            \
    asm volatile("ldmatrix.sync.aligned.m8n8.x4.shared.b16 {%0,%1,%2,%3}, [%4];" \
                 : "=r"(r0), "=r"(r1), "=r"(r2), "=r"(r3) : "r"(addr))

#define LDSM_X4T(r0, r1, r2, r3, addr)                                                 \
    asm volatile("ldmatrix.sync.aligned.m8n8.x4.trans.shared.b16 {%0,%1,%2,%3}, [%4];" \
                 : "=r"(r0), "=r"(r1), "=r"(r2), "=r"(r3) : "r"(addr))

__device__ __forceinline__ void mma_fp16(float* c, const uint32_t* a, const uint32_t* b) {
    asm volatile(
        "mma.sync.aligned.m16n8k16.row.col.f32.f16.f16.f32 "
        "{%0,%1,%2,%3}, {%4,%5,%6,%7}, {%8,%9}, {%0,%1,%2,%3};"
        : "+f"(c[0]), "+f"(c[1]), "+f"(c[2]), "+f"(c[3])
        : "r"(a[0]), "r"(a[1]), "r"(a[2]), "r"(a[3]), "r"(b[0]), "r"(b[1]));
}

// ======================= scratch =======================
__device__ float  g_pre11[(size_t)N_NODES * IN_DIM];     // layer0 aggregate out (fp32)
__device__ __half g_preh[(size_t)N_NODES * HID];         // HID-layer aggregate out (fp16)
__device__ __half g_tmp[(size_t)N_NODES * HID];          // GEMM out pre-BN (fp16)
__device__ __half g_hA[(size_t)N_NODES * HID];           // h buffers (fp16)
__device__ __half g_hB[(size_t)N_NODES * HID];

__device__ int g_deg[N_NODES];
__device__ int g_rowptr[N_NODES + 1];
__device__ int g_cursor[N_NODES + 1];
__device__ uint4 g_epk[N_EDGES];                         // packed: {src, h2(e0,e1), h2(e2,0), pad}
__device__ int g_gptr[N_GRAPHS + 1];

__device__ float g_stats[5 * 2 * HID];
__device__ float g_pool[(size_t)N_GRAPHS * HID];
__device__ __half g_z2[(size_t)N_GRAPHS * HID];

// pre-rounded fp16 weights: 12 slots of [128][128]
__device__ __half g_wh[12 * 128 * 128];

// ======================= init =======================
__global__ void init_k(const float* __restrict__ w1_0, const float* __restrict__ w2_0,
                       const float* __restrict__ w1, const float* __restrict__ w2,
                       const float* __restrict__ hw1, const float* __restrict__ hw2,
                       __half* __restrict__ wh,
                       int* __restrict__ deg, float* __restrict__ stats) {
    int idx = blockIdx.x * 256 + threadIdx.x;
    if (idx < N_NODES) deg[idx] = 0;
    if (idx < 5 * 2 * HID) stats[idx] = 0.f;
    if (idx >= 12 * 16384) return;
    int slot = idx >> 14, off = idx & 16383;
    int k = off >> 7;
    float v = 0.f;
    if (slot == 0) { if (k < IN_DIM) v = w1_0[off]; }
    else if (slot == 1) v = w2_0[off];
    else if (slot < 6) v = w1[(slot - 2) * 16384 + off];
    else if (slot < 10) v = w2[(slot - 6) * 16384 + off];
    else if (slot == 10) v = hw1[off];
    else v = hw2[off];
    wh[idx] = __float2half_rn(v);
}

// ======================= CSR build =======================
__global__ void count_deg_k(const int* __restrict__ dst, int* __restrict__ deg) {
    int e = blockIdx.x * blockDim.x + threadIdx.x;
    if (e < N_EDGES) atomicAdd(&deg[dst[e]], 1);
}

__global__ void scan_csr_k(const int* __restrict__ deg, int* __restrict__ rowptr,
                           int* __restrict__ cursor) {
    __shared__ int warpS[32];
    __shared__ int warpOff[32];
    __shared__ int carryS;
    int tid = threadIdx.x, lane = tid & 31, w = tid >> 5;
    if (tid == 0) { carryS = 0; rowptr[0] = 0; }
    __syncthreads();
    for (int base = 0; base < N_NODES; base += 1024) {
        int i = base + tid;
        int v = (i < N_NODES) ? deg[i] : 0;
        int x = v;
        #pragma unroll
        for (int o = 1; o < 32; o <<= 1) {
            int t = __shfl_up_sync(0xFFFFFFFFu, x, o);
            if (lane >= o) x += t;
        }
        if (lane == 31) warpS[w] = x;
        __syncthreads();
        if (w == 0) {
            int y = warpS[lane];
            int z = y;
            #pragma unroll
            for (int o = 1; o < 32; o <<= 1) {
                int t = __shfl_up_sync(0xFFFFFFFFu, z, o);
                if (lane >= o) z += t;
            }
            warpOff[lane] = z - y;
            if (lane == 31) warpS[0] = z;
        }
        __syncthreads();
        int c = carryS;
        int incl = x + warpOff[w];
        if (i < N_NODES) {
            rowptr[i + 1] = c + incl;
            cursor[i] = c + incl - v;
        }
        int chunkTot = warpS[0];
        __syncthreads();
        if (tid == 0) carryS = c + chunkTot;
        __syncthreads();
    }
}

__global__ void fill_csr_k(const int* __restrict__ src, const int* __restrict__ dst,
                           const float* __restrict__ ea, int* __restrict__ cursor,
                           uint4* __restrict__ epk) {
    int e = blockIdx.x * blockDim.x + threadIdx.x;
    if (e < N_EDGES) {
        int p = atomicAdd(&cursor[dst[e]], 1);
        float a0 = ea[(size_t)e * 3];
        float a1 = ea[(size_t)e * 3 + 1];
        float a2 = ea[(size_t)e * 3 + 2];
        __half2 e01 = __floats2half2_rn(a0, a1);
        __half2 e2z = __floats2half2_rn(a2, 0.f);
        uint4 rec;
        rec.x = (uint32_t)src[e];
        rec.y = *(uint32_t*)&e01;
        rec.z = *(uint32_t*)&e2z;
        rec.w = 0u;
        epk[p] = rec;
    }
}

// ======================= aggregation =======================
__global__ void aggregate11_k(const float* __restrict__ h, const uint4* __restrict__ epk,
                              const float* __restrict__ ew, const float* __restrict__ eb,
                              const float* __restrict__ epsp,
                              const int* __restrict__ rowptr,
                              float* __restrict__ out) {
    int n = blockIdx.x * 4 + (threadIdx.x >> 5);
    int d = threadIdx.x & 31;
    if (n >= N_NODES || d >= IN_DIM) return;
    float w0 = ew[d], w1 = ew[IN_DIM + d], w2 = ew[2 * IN_DIM + d], b = eb[d];
    int s0 = rowptr[n], s1 = rowptr[n + 1];
    float acc = 0.f;
    for (int p = s0; p < s1; p++) {
        uint4 rec = __ldg(epk + p);
        int i0 = (int)rec.x;
        float2 e01 = __half22float2(*(__half2*)&rec.y);
        float e2 = __half2float(*(__half*)&rec.z);
        acc += fmaxf(h[(size_t)i0 * IN_DIM + d] + e01.x * w0 + e01.y * w1 + e2 * w2 + b, 0.f);
    }
    float eps = *epsp;
    out[(size_t)n * IN_DIM + d] = (1.f + eps) * h[(size_t)n * IN_DIM + d] + acc;
}

// warp-per-node; h fp16 (row = 32 uint2); lane owns dims 4*lane..4*lane+3.
// One uint4 packed-edge load + one uint2 gather per edge.
__global__ void __launch_bounds__(256)
aggregate128_k(const uint2* __restrict__ h2, const uint4* __restrict__ epk,
               const float* __restrict__ ew, const float* __restrict__ eb,
               const float* __restrict__ epsp,
               const int* __restrict__ rowptr,
               uint2* __restrict__ pre2) {
    int n = blockIdx.x * 8 + (threadIdx.x >> 5);
    int lane = threadIdx.x & 31;
    if (n >= N_NODES) return;
    float4 w0 = __ldg((const float4*)ew + lane);
    float4 w1 = __ldg((const float4*)(ew + HID) + lane);
    float4 w2 = __ldg((const float4*)(ew + 2 * HID) + lane);
    float4 bb = __ldg((const float4*)eb + lane);
    int s0 = rowptr[n], s1 = rowptr[n + 1];
    float ax = 0.f, ay = 0.f, az = 0.f, aw = 0.f;
    int p = s0;
    for (; p + 4 <= s1; p += 4) {
        uint4 q0 = __ldg(epk + p), q1 = __ldg(epk + p + 1);
        uint4 q2 = __ldg(epk + p + 2), q3 = __ldg(epk + p + 3);
        uint2 r0 = __ldg(h2 + (size_t)q0.x * 32 + lane);
        uint2 r1 = __ldg(h2 + (size_t)q1.x * 32 + lane);
        uint2 r2 = __ldg(h2 + (size_t)q2.x * 32 + lane);
        uint2 r3 = __ldg(h2 + (size_t)q3.x * 32 + lane);
        float2 e01; float e2;
        float2 g01, g23;
        float c0, c1, c2, c3;
        e01 = __half22float2(*(__half2*)&q0.y); e2 = __half2float(*(__half*)&q0.z);
        g01 = __half22float2(*(__half2*)&r0.x);
        g23 = __half22float2(*(__half2*)&r0.y);
        c0 = e01.x * w0.x + e01.y * w1.x + e2 * w2.x + bb.x;
        c1 = e01.x * w0.y + e01.y * w1.y + e2 * w2.y + bb.y;
        c2 = e01.x * w0.z + e01.y * w1.z + e2 * w2.z + bb.z;
        c3 = e01.x * w0.w + e01.y * w1.w + e2 * w2.w + bb.w;
        ax += fmaxf(g01.x + c0, 0.f); ay += fmaxf(g01.y + c1, 0.f);
        az += fmaxf(g23.x + c2, 0.f); aw += fmaxf(g23.y + c3, 0.f);
        e01 = __half22float2(*(__half2*)&q1.y); e2 = __half2float(*(__half*)&q1.z);
        g01 = __half22float2(*(__half2*)&r1.x);
        g23 = __half22float2(*(__half2*)&r1.y);
        c0 = e01.x * w0.x + e01.y * w1.x + e2 * w2.x + bb.x;
        c1 = e01.x * w0.y + e01.y * w1.y + e2 * w2.y + bb.y;
        c2 = e01.x * w0.z + e01.y * w1.z + e2 * w2.z + bb.z;
        c3 = e01.x * w0.w + e01.y * w1.w + e2 * w2.w + bb.w;
        ax += fmaxf(g01.x + c0, 0.f); ay += fmaxf(g01.y + c1, 0.f);
        az += fmaxf(g23.x + c2, 0.f); aw += fmaxf(g23.y + c3, 0.f);
        e01 = __half22float2(*(__half2*)&q2.y); e2 = __half2float(*(__half*)&q2.z);
        g01 = __half22float2(*(__half2*)&r2.x);
        g23 = __half22float2(*(__half2*)&r2.y);
        c0 = e01.x * w0.x + e01.y * w1.x + e2 * w2.x + bb.x;
        c1 = e01.x * w0.y + e01.y * w1.y + e2 * w2.y + bb.y;
        c2 = e01.x * w0.z + e01.y * w1.z + e2 * w2.z + bb.z;
        c3 = e01.x * w0.w + e01.y * w1.w + e2 * w2.w + bb.w;
        ax += fmaxf(g01.x + c0, 0.f); ay += fmaxf(g01.y + c1, 0.f);
        az += fmaxf(g23.x + c2, 0.f); aw += fmaxf(g23.y + c3, 0.f);
        e01 = __half22float2(*(__half2*)&q3.y); e2 = __half2float(*(__half*)&q3.z);
        g01 = __half22float2(*(__half2*)&r3.x);
        g23 = __half22float2(*(__half2*)&r3.y);
        c0 = e01.x * w0.x + e01.y * w1.x + e2 * w2.x + bb.x;
        c1 = e01.x * w0.y + e01.y * w1.y + e2 * w2.y + bb.y;
        c2 = e01.x * w0.z + e01.y * w1.z + e2 * w2.z + bb.z;
        c3 = e01.x * w0.w + e01.y * w1.w + e2 * w2.w + bb.w;
        ax += fmaxf(g01.x + c0, 0.f); ay += fmaxf(g01.y + c1, 0.f);
        az += fmaxf(g23.x + c2, 0.f); aw += fmaxf(g23.y + c3, 0.f);
    }
    for (; p < s1; p++) {
        uint4 q0 = __ldg(epk + p);
        uint2 r0 = __ldg(h2 + (size_t)q0.x * 32 + lane);
        float2 e01 = __half22float2(*(__half2*)&q0.y);
        float e2 = __half2float(*(__half*)&q0.z);
        float2 g01 = __half22float2(*(__half2*)&r0.x);
        float2 g23 = __half22float2(*(__half2*)&r0.y);
        ax += fmaxf(g01.x + e01.x * w0.x + e01.y * w1.x + e2 * w2.x + bb.x, 0.f);
        ay += fmaxf(g01.y + e01.x * w0.y + e01.y * w1.y + e2 * w2.y + bb.y, 0.f);
        az += fmaxf(g23.x + e01.x * w0.z + e01.y * w1.z + e2 * w2.z + bb.z, 0.f);
        aw += fmaxf(g23.y + e01.x * w0.w + e01.y * w1.w + e2 * w2.w + bb.w, 0.f);
    }
    float eps1 = 1.f + *epsp;
    uint2 rn = __ldg(h2 + (size_t)n * 32 + lane);
    float2 hn01 = __half22float2(*(__half2*)&rn.x);
    float2 hn23 = __half22float2(*(__half2*)&rn.y);
    __half2 o01 = __floats2half2_rn(eps1 * hn01.x + ax, eps1 * hn01.y + ay);
    __half2 o23 = __floats2half2_rn(eps1 * hn23.x + az, eps1 * hn23.y + aw);
    uint2 ov;
    ov.x = *(uint32_t*)&o01;
    ov.y = *(uint32_t*)&o23;
    pre2[(size_t)n * 32 + lane] = ov;
}

// ======================= fused 2-GEMM MLP (pure fp16, M=64, 4 CTAs/SM) =======================
#define APAD 136
#define SX      0
#define SY      17408
#define S_B1    52224
#define S_B2    52736
#define S_STAT  53248
#define SM_TOTAL (S_STAT + 2048)
#define STG_PITCH 130

// a_mode: 0 = fp32 scalar (layer0, pitch IN_DIM), 1 = fp32 float4 (head), 2 = fp16 direct
__global__ void __launch_bounds__(256, 4)
gemm_mlp_k(const void* __restrict__ Av, int M, int a_mode,
           const __half* __restrict__ W1, const float* __restrict__ b1,
           const __half* __restrict__ W2, const float* __restrict__ b2,
           __half* __restrict__ C, int do_relu2,
           float* __restrict__ ssum, float* __restrict__ ssq, int nsteps1) {
    extern __shared__ __align__(16) char smem[];
    __half* aS = (__half*)(smem + SX);
    __half* wS = (__half*)(smem + SY);
    float* b1S = (float*)(smem + S_B1);
    float* b2S = (float*)(smem + S_B2);
    float* statS = (float*)(smem + S_STAT);

    int tid = threadIdx.x;
    int lane = tid & 31;
    int wid = tid >> 5;
    int rowBase = blockIdx.x * 64;
    int kmax1 = nsteps1 << 4;

    if (tid < HID) { b1S[tid] = b1[tid]; b2S[tid] = b2[tid]; }

    // ---- load A [64 x kmax1] ----
    if (a_mode == 2) {
        const __half* Ah = (const __half*)Av;
        const uint4 Z4 = make_uint4(0u, 0u, 0u, 0u);
        for (int idx = tid; idx < 64 * 16; idx += 256) {
            int r = idx >> 4, seg = idx & 15;
            int gr = rowBase + r;
            uint4 v = (gr < M) ? __ldg((const uint4*)(Ah + (size_t)gr * HID) + seg) : Z4;
            *(uint4*)&aS[r * APAD + seg * 8] = v;
        }
    } else if (a_mode == 1) {
        const float* A = (const float*)Av;
        for (int idx = tid; idx < 64 * 32; idx += 256) {
            int r = idx >> 5, seg = idx & 31;
            int gr = rowBase + r;
            float4 v = (gr < M) ? __ldg((const float4*)(A + (size_t)gr * HID) + seg)
                                : make_float4(0.f, 0.f, 0.f, 0.f);
            __half2* ph = (__half2*)&aS[r * APAD + seg * 4];
            ph[0] = __halves2half2(__float2half_rn(v.x), __float2half_rn(v.y));
            ph[1] = __halves2half2(__float2half_rn(v.z), __float2half_rn(v.w));
        }
    } else {
        const float* A = (const float*)Av;
        for (int idx = tid; idx < 64 * 16; idx += 256) {
            int r = idx >> 4, k = idx & 15;
            int gr = rowBase + r;
            float a = (gr < M && k < IN_DIM) ? __ldg(A + (size_t)gr * IN_DIM + k) : 0.f;
            aS[r * APAD + k] = __float2half_rn(a);
        }
    }
    for (int idx = tid; idx < kmax1 * 16; idx += 256) {
        int k = idx >> 4, seg = idx & 15;
        *(uint4*)&wS[k * APAD + seg * 8] = __ldg((const uint4*)(W1 + k * HID) + seg);
    }
    __syncthreads();

    int warpR = (wid >> 2) << 5;
    int warpC = (wid & 3) << 5;
    uint32_t aBase = smem_u32(aS);
    uint32_t wBase = smem_u32(wS);
    float acc[2][4][4];

    #pragma unroll
    for (int m = 0; m < 2; m++)
        #pragma unroll
        for (int j = 0; j < 4; j++)
            #pragma unroll
            for (int q = 0; q < 4; q++) acc[m][j][q] = 0.f;

    // ================= pass 1 =================
    for (int s = 0; s < nsteps1; s++) {
        int k0 = s << 4;
        uint32_t aAddr = aBase +
            ((uint32_t)((warpR + (lane & 15)) * APAD + k0 + ((lane >> 4) << 3)) << 1);
        uint32_t a0[4], a1[4];
        LDSM_X4(a0[0], a0[1], a0[2], a0[3], aAddr);
        LDSM_X4(a1[0], a1[1], a1[2], a1[3], aAddr + 16 * APAD * 2);

        uint32_t bAddr = wBase +
            ((uint32_t)((k0 + (lane & 7) + ((lane >> 3) & 1) * 8) * APAD +
                        warpC + ((lane >> 4) << 3)) << 1);
        uint32_t bf[4][2];
        #pragma unroll
        for (int pp = 0; pp < 2; pp++) {
            uint32_t r0, r1, r2, r3;
            LDSM_X4T(r0, r1, r2, r3, bAddr + pp * 32);
            bf[2 * pp][0] = r0; bf[2 * pp][1] = r1;
            bf[2 * pp + 1][0] = r2; bf[2 * pp + 1][1] = r3;
        }
        #pragma unroll
        for (int j = 0; j < 4; j++) {
            mma_fp16(acc[0][j], a0, bf[j]);
            mma_fp16(acc[1][j], a1, bf[j]);
        }
    }
    __syncthreads();

    // ---- T1 = relu(acc + b1) -> fp16 into A region; load W2 ----
    #pragma unroll
    for (int m = 0; m < 2; m++) {
        #pragma unroll
        for (int j = 0; j < 4; j++) {
            #pragma unroll
            for (int q = 0; q < 4; q++) {
                int row = warpR + m * 16 + (lane >> 2) + ((q >> 1) << 3);
                int col = warpC + j * 8 + ((lane & 3) << 1) + (q & 1);
                float t = fmaxf(acc[m][j][q] + b1S[col], 0.f);
                aS[row * APAD + col] = __float2half_rn(t);
            }
        }
    }
    for (int idx = tid; idx < 128 * 16; idx += 256) {
        int k = idx >> 4, seg = idx & 15;
        *(uint4*)&wS[k * APAD + seg * 8] = __ldg((const uint4*)(W2 + k * HID) + seg);
    }
    __syncthreads();

    // ================= pass 2 (K = 128) =================
    #pragma unroll
    for (int m = 0; m < 2; m++)
        #pragma unroll
        for (int j = 0; j < 4; j++)
            #pragma unroll
            for (int q = 0; q < 4; q++) acc[m][j][q] = 0.f;

    for (int s = 0; s < 8; s++) {
        int k0 = s << 4;
        uint32_t aAddr = aBase +
            ((uint32_t)((warpR + (lane & 15)) * APAD + k0 + ((lane >> 4) << 3)) << 1);
        uint32_t a0[4], a1[4];
        LDSM_X4(a0[0], a0[1], a0[2], a0[3], aAddr);
        LDSM_X4(a1[0], a1[1], a1[2], a1[3], aAddr + 16 * APAD * 2);

        uint32_t bAddr = wBase +
            ((uint32_t)((k0 + (lane & 7) + ((lane >> 3) & 1) * 8) * APAD +
                        warpC + ((lane >> 4) << 3)) << 1);
        uint32_t bf[4][2];
        #pragma unroll
        for (int pp = 0; pp < 2; pp++) {
            uint32_t r0, r1, r2, r3;
            LDSM_X4T(r0, r1, r2, r3, bAddr + pp * 32);
            bf[2 * pp][0] = r0; bf[2 * pp][1] = r1;
            bf[2 * pp + 1][0] = r2; bf[2 * pp + 1][1] = r3;
        }
        #pragma unroll
        for (int j = 0; j < 4; j++) {
            mma_fp16(acc[0][j], a0, bf[j]);
            mma_fp16(acc[1][j], a1, bf[j]);
        }
    }
    __syncthreads();

    float* stg = (float*)smem;
    #pragma unroll
    for (int m = 0; m < 2; m++) {
        #pragma unroll
        for (int j = 0; j < 4; j++) {
            int row = warpR + m * 16 + (lane >> 2);
            int col = warpC + j * 8 + ((lane & 3) << 1);
            stg[row * STG_PITCH + col]       = acc[m][j][0];
            stg[row * STG_PITCH + col + 1]   = acc[m][j][1];
            stg[(row + 8) * STG_PITCH + col]     = acc[m][j][2];
            stg[(row + 8) * STG_PITCH + col + 1] = acc[m][j][3];
        }
    }
    __syncthreads();

    // ---- coalesced fp16 store + bias2/relu2 + fused BN stats (stats from fp32) ----
    {
        int c = tid & 127, hh = tid >> 7;
        float bia = b2S[c];
        float s0 = 0.f, q0 = 0.f;
        #pragma unroll 4
        for (int j = 0; j < 32; j++) {
            int r = hh * 32 + j;
            int gr = rowBase + r;
            if (gr < M) {
                float v = stg[r * STG_PITCH + c] + bia;
                if (do_relu2) v = fmaxf(v, 0.f);
                C[(size_t)gr * HID + c] = __float2half_rn(v);
                s0 += v;
                q0 += v * v;
            }
        }
        if (ssum) {
            statS[hh * 128 + c] = s0;
            statS[256 + hh * 128 + c] = q0;
            __syncthreads();
            if (tid < 128) {
                atomicAdd(&ssum[tid], statS[tid] + statS[128 + tid]);
                atomicAdd(&ssq[tid], statS[256 + tid] + statS[384 + tid]);
            }
        }
    }
}

// ======================= BN + relu + optional residual (fp16 in/out) =======================
__global__ void bn_relu_res_k(const uint2* __restrict__ tmp, const float* __restrict__ stats,
                              const float* __restrict__ gamma, const float* __restrict__ beta,
                              const uint2* __restrict__ res, uint2* __restrict__ out,
                              int n_rows) {
    size_t i = (size_t)blockIdx.x * blockDim.x + threadIdx.x;
    size_t total = (size_t)n_rows * 32;
    if (i >= total) return;
    int d = ((int)(i & 31)) << 2;
    float invN = 1.f / (float)n_rows;
    uint2 tv = tmp[i];
    float2 t01 = __half22float2(*(__half2*)&tv.x);
    float2 t23 = __half22float2(*(__half2*)&tv.y);
    float ox, oy, oz, ow;
    {
        float mu = stats[d] * invN;
        float var = stats[HID + d] * invN - mu * mu;
        ox = fmaxf((t01.x - mu) * rsqrtf(var + BN_EPS) * gamma[d] + beta[d], 0.f);
    }
    {
        float mu = stats[d + 1] * invN;
        float var = stats[HID + d + 1] * invN - mu * mu;
        oy = fmaxf((t01.y - mu) * rsqrtf(var + BN_EPS) * gamma[d + 1] + beta[d + 1], 0.f);
    }
    {
        float mu = stats[d + 2] * invN;
        float var = stats[HID + d + 2] * invN - mu * mu;
        oz = fmaxf((t23.x - mu) * rsqrtf(var + BN_EPS) * gamma[d + 2] + beta[d + 2], 0.f);
    }
    {
        float mu = stats[d + 3] * invN;
        float var = stats[HID + d + 3] * invN - mu * mu;
        ow = fmaxf((t23.y - mu) * rsqrtf(var + BN_EPS) * gamma[d + 3] + beta[d + 3], 0.f);
    }
    if (res) {
        uint2 rv = res[i];
        float2 r01 = __half22float2(*(__half2*)&rv.x);
        float2 r23 = __half22float2(*(__half2*)&rv.y);
        ox += r01.x; oy += r01.y; oz += r23.x; ow += r23.y;
    }
    __half2 o01 = __floats2half2_rn(ox, oy);
    __half2 o23 = __floats2half2_rn(oz, ow);
    uint2 ov;
    ov.x = *(uint32_t*)&o01;
    ov.y = *(uint32_t*)&o23;
    out[i] = ov;
}

// ======================= pooling =======================
__global__ void graph_ptr_k(const int* __restrict__ batch, int* __restrict__ gptr) {
    int g = blockIdx.x * blockDim.x + threadIdx.x;
    if (g > N_GRAPHS) return;
    int lo = 0, hi = N_NODES;
    while (lo < hi) {
        int mid = (lo + hi) >> 1;
        if (batch[mid] < g) lo = mid + 1; else hi = mid;
    }
    gptr[g] = lo;
}
__global__ void pool_k(const __half* __restrict__ h, const int* __restrict__ gptr,
                       float* __restrict__ pooled) {
    int g = blockIdx.x;
    int d = threadIdx.x;
    int a = gptr[g], b = gptr[g + 1];
    float acc = 0.f;
    for (int n = a; n < b; n++) acc += __half2float(h[(size_t)n * HID + d]);
    int cnt = b - a;
    float c = (float)(cnt > 1 ? cnt : 1);
    pooled[(size_t)g * HID + d] = acc / c;
}

// ======================= head final dot (fp16 z) =======================
__global__ void head_out_k(const __half* __restrict__ z, const float* __restrict__ w,
                           const float* __restrict__ b, float* __restrict__ out) {
    int g = blockIdx.x;
    int t = threadIdx.x; // 128
    float v = __half2float(z[(size_t)g * HID + t]) * w[t];
    #pragma unroll
    for (int off = 16; off; off >>= 1) v += __shfl_down_sync(0xFFFFFFFFu, v, off);
    __shared__ float s[4];
    if ((t & 31) == 0) s[t >> 5] = v;
    __syncthreads();
    if (t == 0) out[g] = s[0] + s[1] + s[2] + s[3] + b[0];
}

// ======================= host =======================
static void* sym_addr(const void* sym) {
    void* p = nullptr;
    cudaGetSymbolAddress(&p, sym);
    return p;
}

extern "C" void kernel_launch(void* const* d_in, const int* in_sizes, int n_in,
                              void* d_out, int out_size) {
    const float* x        = (const float*)d_in[0];
    const float* edge_attr= (const float*)d_in[1];
    const float* e_w0     = (const float*)d_in[2];
    const float* e_b0     = (const float*)d_in[3];
    const float* w1_0     = (const float*)d_in[4];
    const float* b1_0     = (const float*)d_in[5];
    const float* w2_0     = (const float*)d_in[6];
    const float* b2_0     = (const float*)d_in[7];
    const float* gamma0   = (const float*)d_in[8];
    const float* beta0    = (const float*)d_in[9];
    const float* eps0     = (const float*)d_in[10];
    const float* e_w      = (const float*)d_in[11];
    const float* e_b      = (const float*)d_in[12];
    const float* w1       = (const float*)d_in[13];
    const float* b1       = (const float*)d_in[14];
    const float* w2       = (const float*)d_in[15];
    const float* b2       = (const float*)d_in[16];
    const float* gamma    = (const float*)d_in[17];
    const float* beta     = (const float*)d_in[18];
    const float* eps_r    = (const float*)d_in[19];
    const float* hw1      = (const float*)d_in[20];
    const float* hb1      = (const float*)d_in[21];
    const float* hw2      = (const float*)d_in[22];
    const float* hb2      = (const float*)d_in[23];
    const float* hw3      = (const float*)d_in[24];
    const float* hb3      = (const float*)d_in[25];
    const int*   edge_index = (const int*)d_in[26];
    const int*   batch    = (const int*)d_in[27];

    const int* src = edge_index;
    const int* dst = edge_index + N_EDGES;

    float* pre11 = (float*)sym_addr(g_pre11);
    __half* preh = (__half*)sym_addr(g_preh);
    __half* tmp  = (__half*)sym_addr(g_tmp);
    __half* hA   = (__half*)sym_addr(g_hA);
    __half* hB   = (__half*)sym_addr(g_hB);
    int*   deg   = (int*)sym_addr(g_deg);
    int*   rowptr= (int*)sym_addr(g_rowptr);
    int*   cursor= (int*)sym_addr(g_cursor);
    uint4* epk   = (uint4*)sym_addr(g_epk);
    int*   gptr  = (int*)sym_addr(g_gptr);
    float* stats = (float*)sym_addr(g_stats);
    float* pool  = (float*)sym_addr(g_pool);
    __half* z2   = (__half*)sym_addr(g_z2);
    __half* wh   = (__half*)sym_addr(g_wh);
    float* out   = (float*)d_out;

    cudaFuncSetAttribute(gemm_mlp_k, cudaFuncAttributeMaxDynamicSharedMemorySize, SM_TOTAL);

    const int SLOT = 128 * 128;

    init_k<<<(12 * 16384 + 255) / 256, 256>>>(w1_0, w2_0, w1, w2, hw1, hw2, wh, deg, stats);
    count_deg_k<<<(N_EDGES + 255) / 256, 256>>>(dst, deg);
    scan_csr_k<<<1, 1024>>>(deg, rowptr, cursor);
    fill_csr_k<<<(N_EDGES + 255) / 256, 256>>>(src, dst, edge_attr, cursor, epk);

    const int GB_N = (N_NODES + 63) / 64;
    const int GB_G = (N_GRAPHS + 63) / 64;
    const int BN_BLOCKS = (int)(((size_t)N_NODES * 32 + 255) / 256);

    // ---- layer 0 ----
    aggregate11_k<<<(N_NODES + 3) / 4, 128>>>(x, epk, e_w0, e_b0, eps0, rowptr, pre11);
    gemm_mlp_k<<<GB_N, 256, SM_TOTAL>>>(pre11, N_NODES, 0,
                                        wh + 0 * SLOT, b1_0,
                                        wh + 1 * SLOT, b2_0,
                                        tmp, 0, stats, stats + HID, 1);
    bn_relu_res_k<<<BN_BLOCKS, 256>>>((const uint2*)tmp, stats, gamma0, beta0,
                                      nullptr, (uint2*)hA, N_NODES);

    // ---- layers 1..4 ----
    __half* cur = hA;
    __half* nxt = hB;
    for (int i = 0; i < N_REST; i++) {
        float* st = stats + (size_t)(1 + i) * 2 * HID;
        aggregate128_k<<<(N_NODES + 7) / 8, 256>>>((const uint2*)cur, epk,
                                                   e_w + (size_t)i * 3 * HID,
                                                   e_b + (size_t)i * HID, eps_r + i,
                                                   rowptr, (uint2*)preh);
        gemm_mlp_k<<<GB_N, 256, SM_TOTAL>>>(preh, N_NODES, 2,
                                            wh + (2 + i) * SLOT, b1 + (size_t)i * HID,
                                            wh + (6 + i) * SLOT, b2 + (size_t)i * HID,
                                            tmp, 0, st, st + HID, 8);
        bn_relu_res_k<<<BN_BLOCKS, 256>>>((const uint2*)tmp, st,
                                          gamma + (size_t)i * HID, beta + (size_t)i * HID,
                                          (const uint2*)cur, (uint2*)nxt, N_NODES);
        __half* t = cur; cur = nxt; nxt = t;
    }

    // ---- pooling ----
    graph_ptr_k<<<(N_GRAPHS + 1 + 127) / 128, 128>>>(batch, gptr);
    pool_k<<<N_GRAPHS, HID>>>(cur, gptr, pool);

    // ---- head ----
    gemm_mlp_k<<<GB_G, 256, SM_TOTAL>>>(pool, N_GRAPHS, 1,
                                        wh + 10 * SLOT, hb1,
                                        wh + 11 * SLOT, hb2,
                                        z2, 1, nullptr, nullptr, 8);
    head_out_k<<<N_GRAPHS, HID>>>(z2, hw3, hb3, out);
}

// round 16
// speedup vs baseline: 1.0557x; 1.0557x over previous
#include <cuda_runtime.h>
#include <cuda_fp16.h>
#include <cstdint>

#define N_NODES 100000
#define N_EDGES 600000
#define N_GRAPHS 5000
#define IN_DIM 11
#define HID 128
#define EDGE_DIM 3
#define N_REST 4
#define BN_EPS 1e-5f

// ======================= PTX helpers (baseline sm_80+ ISA only) =======================
__device__ __forceinline__ uint32_t smem_u32(const void* p) {
    uint32_t a;
    asm("{ .reg .u64 t; cvta.to.shared.u64 t, %1; cvt.u32.u64 %0, t; }" : "=r"(a) : "l"(p));
    return a;
}

#define LDSM_X4(r0, r1, r2, r3, addr)                                            \
    asm volatile("ldmatrix.sync.aligned.m8n8.x4.shared.b16 {%0,%1,%2,%3}, [%4];" \
                 : "=r"(r0), "=r"(r1), "=r"(r2), "=r"(r3) : "r"(addr))

#define LDSM_X4T(r0, r1, r2, r3, addr)                                                 \
    asm volatile("ldmatrix.sync.aligned.m8n8.x4.trans.shared.b16 {%0,%1,%2,%3}, [%4];" \
                 : "=r"(r0), "=r"(r1), "=r"(r2), "=r"(r3) : "r"(addr))

__device__ __forceinline__ void mma_fp16(float* c, const uint32_t* a, const uint32_t* b) {
    asm volatile(
        "mma.sync.aligned.m16n8k16.row.col.f32.f16.f16.f32 "
        "{%0,%1,%2,%3}, {%4,%5,%6,%7}, {%8,%9}, {%0,%1,%2,%3};"
        : "+f"(c[0]), "+f"(c[1]), "+f"(c[2]), "+f"(c[3])
        : "r"(a[0]), "r"(a[1]), "r"(a[2]), "r"(a[3]), "r"(b[0]), "r"(b[1]));
}

// ======================= scratch =======================
__device__ float  g_pre11[(size_t)N_NODES * IN_DIM];     // layer0 aggregate out (fp32)
__device__ __half g_preh[(size_t)N_NODES * HID];         // HID-layer aggregate out (fp16)
__device__ __half g_tmp[(size_t)N_NODES * HID];          // GEMM out pre-BN (fp16)
__device__ __half g_hA[(size_t)N_NODES * HID];           // h buffers (fp16)
__device__ __half g_hB[(size_t)N_NODES * HID];

__device__ int g_deg[N_NODES];
__device__ int g_rowptr[N_NODES + 1];
__device__ int g_cursor[N_NODES + 1];
__device__ int g_srcp[N_EDGES];                          // permuted src (separate dense stream)
__device__ uint2 g_eah[N_EDGES];                         // permuted edge attrs fp16 {h2(e0,e1), h2(e2,0)}
__device__ int g_gptr[N_GRAPHS + 1];

__device__ float g_stats[5 * 2 * HID];
__device__ float g_pool[(size_t)N_GRAPHS * HID];
__device__ __half g_z2[(size_t)N_GRAPHS * HID];

// pre-rounded fp16 weights: 12 slots of [128][128]
__device__ __half g_wh[12 * 128 * 128];

// ======================= init =======================
__global__ void init_k(const float* __restrict__ w1_0, const float* __restrict__ w2_0,
                       const float* __restrict__ w1, const float* __restrict__ w2,
                       const float* __restrict__ hw1, const float* __restrict__ hw2,
                       __half* __restrict__ wh,
                       int* __restrict__ deg, float* __restrict__ stats) {
    int idx = blockIdx.x * 256 + threadIdx.x;
    if (idx < N_NODES) deg[idx] = 0;
    if (idx < 5 * 2 * HID) stats[idx] = 0.f;
    if (idx >= 12 * 16384) return;
    int slot = idx >> 14, off = idx & 16383;
    int k = off >> 7;
    float v = 0.f;
    if (slot == 0) { if (k < IN_DIM) v = w1_0[off]; }
    else if (slot == 1) v = w2_0[off];
    else if (slot < 6) v = w1[(slot - 2) * 16384 + off];
    else if (slot < 10) v = w2[(slot - 6) * 16384 + off];
    else if (slot == 10) v = hw1[off];
    else v = hw2[off];
    wh[idx] = __float2half_rn(v);
}

// ======================= CSR build =======================
__global__ void count_deg_k(const int* __restrict__ dst, int* __restrict__ deg) {
    int e = blockIdx.x * blockDim.x + threadIdx.x;
    if (e < N_EDGES) atomicAdd(&deg[dst[e]], 1);
}

__global__ void scan_csr_k(const int* __restrict__ deg, int* __restrict__ rowptr,
                           int* __restrict__ cursor) {
    __shared__ int warpS[32];
    __shared__ int warpOff[32];
    __shared__ int carryS;
    int tid = threadIdx.x, lane = tid & 31, w = tid >> 5;
    if (tid == 0) { carryS = 0; rowptr[0] = 0; }
    __syncthreads();
    for (int base = 0; base < N_NODES; base += 1024) {
        int i = base + tid;
        int v = (i < N_NODES) ? deg[i] : 0;
        int x = v;
        #pragma unroll
        for (int o = 1; o < 32; o <<= 1) {
            int t = __shfl_up_sync(0xFFFFFFFFu, x, o);
            if (lane >= o) x += t;
        }
        if (lane == 31) warpS[w] = x;
        __syncthreads();
        if (w == 0) {
            int y = warpS[lane];
            int z = y;
            #pragma unroll
            for (int o = 1; o < 32; o <<= 1) {
                int t = __shfl_up_sync(0xFFFFFFFFu, z, o);
                if (lane >= o) z += t;
            }
            warpOff[lane] = z - y;
            if (lane == 31) warpS[0] = z;
        }
        __syncthreads();
        int c = carryS;
        int incl = x + warpOff[w];
        if (i < N_NODES) {
            rowptr[i + 1] = c + incl;
            cursor[i] = c + incl - v;
        }
        int chunkTot = warpS[0];
        __syncthreads();
        if (tid == 0) carryS = c + chunkTot;
        __syncthreads();
    }
}

__global__ void fill_csr_k(const int* __restrict__ src, const int* __restrict__ dst,
                           const float* __restrict__ ea, int* __restrict__ cursor,
                           int* __restrict__ srcp, uint2* __restrict__ eah) {
    int e = blockIdx.x * blockDim.x + threadIdx.x;
    if (e < N_EDGES) {
        int p = atomicAdd(&cursor[dst[e]], 1);
        srcp[p] = src[e];
        __half2 e01 = __floats2half2_rn(ea[(size_t)e * 3], ea[(size_t)e * 3 + 1]);
        __half2 e2z = __floats2half2_rn(ea[(size_t)e * 3 + 2], 0.f);
        uint2 rec;
        rec.x = *(uint32_t*)&e01;
        rec.y = *(uint32_t*)&e2z;
        eah[p] = rec;
    }
}

// ======================= aggregation =======================
__global__ void aggregate11_k(const float* __restrict__ h, const uint2* __restrict__ eah,
                              const float* __restrict__ ew, const float* __restrict__ eb,
                              const float* __restrict__ epsp,
                              const int* __restrict__ srcp, const int* __restrict__ rowptr,
                              float* __restrict__ out) {
    int n = blockIdx.x * 4 + (threadIdx.x >> 5);
    int d = threadIdx.x & 31;
    if (n >= N_NODES || d >= IN_DIM) return;
    float w0 = ew[d], w1 = ew[IN_DIM + d], w2 = ew[2 * IN_DIM + d], b = eb[d];
    int s0 = rowptr[n], s1 = rowptr[n + 1];
    float acc = 0.f;
    for (int p = s0; p < s1; p++) {
        int i0 = __ldg(srcp + p);
        uint2 rec = __ldg(eah + p);
        float2 e01 = __half22float2(*(__half2*)&rec.x);
        float e2 = __half2float(*(__half*)&rec.y);
        acc += fmaxf(h[(size_t)i0 * IN_DIM + d] + e01.x * w0 + e01.y * w1 + e2 * w2 + b, 0.f);
    }
    float eps = *epsp;
    out[(size_t)n * IN_DIM + d] = (1.f + eps) * h[(size_t)n * IN_DIM + d] + acc;
}

// warp-per-node; h fp16 (row = 32 uint2); lane owns dims 4*lane..4*lane+3.
// Separate dense index stream (4B) + fp16 attr stream (8B) + fp16 gather (8B).
__global__ void __launch_bounds__(256)
aggregate128_k(const uint2* __restrict__ h2, const uint2* __restrict__ eah,
               const float* __restrict__ ew, const float* __restrict__ eb,
               const float* __restrict__ epsp,
               const int* __restrict__ srcp, const int* __restrict__ rowptr,
               uint2* __restrict__ pre2) {
    int n = blockIdx.x * 8 + (threadIdx.x >> 5);
    int lane = threadIdx.x & 31;
    if (n >= N_NODES) return;
    float4 w0 = __ldg((const float4*)ew + lane);
    float4 w1 = __ldg((const float4*)(ew + HID) + lane);
    float4 w2 = __ldg((const float4*)(ew + 2 * HID) + lane);
    float4 bb = __ldg((const float4*)eb + lane);
    int s0 = rowptr[n], s1 = rowptr[n + 1];
    float ax = 0.f, ay = 0.f, az = 0.f, aw = 0.f;
    int p = s0;
    for (; p + 4 <= s1; p += 4) {
        int i0 = __ldg(srcp + p), i1 = __ldg(srcp + p + 1);
        int i2 = __ldg(srcp + p + 2), i3 = __ldg(srcp + p + 3);
        uint2 q0 = __ldg(eah + p), q1 = __ldg(eah + p + 1);
        uint2 q2 = __ldg(eah + p + 2), q3 = __ldg(eah + p + 3);
        uint2 r0 = __ldg(h2 + (size_t)i0 * 32 + lane);
        uint2 r1 = __ldg(h2 + (size_t)i1 * 32 + lane);
        uint2 r2 = __ldg(h2 + (size_t)i2 * 32 + lane);
        uint2 r3 = __ldg(h2 + (size_t)i3 * 32 + lane);
        float2 e01; float e2;
        float2 g01, g23;
        float c0, c1, c2, c3;
        e01 = __half22float2(*(__half2*)&q0.x); e2 = __half2float(*(__half*)&q0.y);
        g01 = __half22float2(*(__half2*)&r0.x);
        g23 = __half22float2(*(__half2*)&r0.y);
        c0 = e01.x * w0.x + e01.y * w1.x + e2 * w2.x + bb.x;
        c1 = e01.x * w0.y + e01.y * w1.y + e2 * w2.y + bb.y;
        c2 = e01.x * w0.z + e01.y * w1.z + e2 * w2.z + bb.z;
        c3 = e01.x * w0.w + e01.y * w1.w + e2 * w2.w + bb.w;
        ax += fmaxf(g01.x + c0, 0.f); ay += fmaxf(g01.y + c1, 0.f);
        az += fmaxf(g23.x + c2, 0.f); aw += fmaxf(g23.y + c3, 0.f);
        e01 = __half22float2(*(__half2*)&q1.x); e2 = __half2float(*(__half*)&q1.y);
        g01 = __half22float2(*(__half2*)&r1.x);
        g23 = __half22float2(*(__half2*)&r1.y);
        c0 = e01.x * w0.x + e01.y * w1.x + e2 * w2.x + bb.x;
        c1 = e01.x * w0.y + e01.y * w1.y + e2 * w2.y + bb.y;
        c2 = e01.x * w0.z + e01.y * w1.z + e2 * w2.z + bb.z;
        c3 = e01.x * w0.w + e01.y * w1.w + e2 * w2.w + bb.w;
        ax += fmaxf(g01.x + c0, 0.f); ay += fmaxf(g01.y + c1, 0.f);
        az += fmaxf(g23.x + c2, 0.f); aw += fmaxf(g23.y + c3, 0.f);
        e01 = __half22float2(*(__half2*)&q2.x); e2 = __half2float(*(__half*)&q2.y);
        g01 = __half22float2(*(__half2*)&r2.x);
        g23 = __half22float2(*(__half2*)&r2.y);
        c0 = e01.x * w0.x + e01.y * w1.x + e2 * w2.x + bb.x;
        c1 = e01.x * w0.y + e01.y * w1.y + e2 * w2.y + bb.y;
        c2 = e01.x * w0.z + e01.y * w1.z + e2 * w2.z + bb.z;
        c3 = e01.x * w0.w + e01.y * w1.w + e2 * w2.w + bb.w;
        ax += fmaxf(g01.x + c0, 0.f); ay += fmaxf(g01.y + c1, 0.f);
        az += fmaxf(g23.x + c2, 0.f); aw += fmaxf(g23.y + c3, 0.f);
        e01 = __half22float2(*(__half2*)&q3.x); e2 = __half2float(*(__half*)&q3.y);
        g01 = __half22float2(*(__half2*)&r3.x);
        g23 = __half22float2(*(__half2*)&r3.y);
        c0 = e01.x * w0.x + e01.y * w1.x + e2 * w2.x + bb.x;
        c1 = e01.x * w0.y + e01.y * w1.y + e2 * w2.y + bb.y;
        c2 = e01.x * w0.z + e01.y * w1.z + e2 * w2.z + bb.z;
        c3 = e01.x * w0.w + e01.y * w1.w + e2 * w2.w + bb.w;
        ax += fmaxf(g01.x + c0, 0.f); ay += fmaxf(g01.y + c1, 0.f);
        az += fmaxf(g23.x + c2, 0.f); aw += fmaxf(g23.y + c3, 0.f);
    }
    for (; p < s1; p++) {
        int i0 = __ldg(srcp + p);
        uint2 q0 = __ldg(eah + p);
        uint2 r0 = __ldg(h2 + (size_t)i0 * 32 + lane);
        float2 e01 = __half22float2(*(__half2*)&q0.x);
        float e2 = __half2float(*(__half*)&q0.y);
        float2 g01 = __half22float2(*(__half2*)&r0.x);
        float2 g23 = __half22float2(*(__half2*)&r0.y);
        ax += fmaxf(g01.x + e01.x * w0.x + e01.y * w1.x + e2 * w2.x + bb.x, 0.f);
        ay += fmaxf(g01.y + e01.x * w0.y + e01.y * w1.y + e2 * w2.y + bb.y, 0.f);
        az += fmaxf(g23.x + e01.x * w0.z + e01.y * w1.z + e2 * w2.z + bb.z, 0.f);
        aw += fmaxf(g23.y + e01.x * w0.w + e01.y * w1.w + e2 * w2.w + bb.w, 0.f);
    }
    float eps1 = 1.f + *epsp;
    uint2 rn = __ldg(h2 + (size_t)n * 32 + lane);
    float2 hn01 = __half22float2(*(__half2*)&rn.x);
    float2 hn23 = __half22float2(*(__half2*)&rn.y);
    __half2 o01 = __floats2half2_rn(eps1 * hn01.x + ax, eps1 * hn01.y + ay);
    __half2 o23 = __floats2half2_rn(eps1 * hn23.x + az, eps1 * hn23.y + aw);
    uint2 ov;
    ov.x = *(uint32_t*)&o01;
    ov.y = *(uint32_t*)&o23;
    pre2[(size_t)n * 32 + lane] = ov;
}

// ======================= fused 2-GEMM MLP (pure fp16, M=64, 4 CTAs/SM) =======================
#define APAD 136
#define SX      0
#define SY      17408
#define S_B1    52224
#define S_B2    52736
#define S_STAT  53248
#define SM_TOTAL (S_STAT + 2048)
#define STG_PITCH 130

// a_mode: 0 = fp32 scalar (layer0, pitch IN_DIM), 1 = fp32 float4 (head), 2 = fp16 direct
__global__ void __launch_bounds__(256, 4)
gemm_mlp_k(const void* __restrict__ Av, int M, int a_mode,
           const __half* __restrict__ W1, const float* __restrict__ b1,
           const __half* __restrict__ W2, const float* __restrict__ b2,
           __half* __restrict__ C, int do_relu2,
           float* __restrict__ ssum, float* __restrict__ ssq, int nsteps1) {
    extern __shared__ __align__(16) char smem[];
    __half* aS = (__half*)(smem + SX);
    __half* wS = (__half*)(smem + SY);
    float* b1S = (float*)(smem + S_B1);
    float* b2S = (float*)(smem + S_B2);
    float* statS = (float*)(smem + S_STAT);

    int tid = threadIdx.x;
    int lane = tid & 31;
    int wid = tid >> 5;
    int rowBase = blockIdx.x * 64;
    int kmax1 = nsteps1 << 4;

    if (tid < HID) { b1S[tid] = b1[tid]; b2S[tid] = b2[tid]; }

    // ---- load A [64 x kmax1] ----
    if (a_mode == 2) {
        const __half* Ah = (const __half*)Av;
        const uint4 Z4 = make_uint4(0u, 0u, 0u, 0u);
        for (int idx = tid; idx < 64 * 16; idx += 256) {
            int r = idx >> 4, seg = idx & 15;
            int gr = rowBase + r;
            uint4 v = (gr < M) ? __ldg((const uint4*)(Ah + (size_t)gr * HID) + seg) : Z4;
            *(uint4*)&aS[r * APAD + seg * 8] = v;
        }
    } else if (a_mode == 1) {
        const float* A = (const float*)Av;
        for (int idx = tid; idx < 64 * 32; idx += 256) {
            int r = idx >> 5, seg = idx & 31;
            int gr = rowBase + r;
            float4 v = (gr < M) ? __ldg((const float4*)(A + (size_t)gr * HID) + seg)
                                : make_float4(0.f, 0.f, 0.f, 0.f);
            __half2* ph = (__half2*)&aS[r * APAD + seg * 4];
            ph[0] = __halves2half2(__float2half_rn(v.x), __float2half_rn(v.y));
            ph[1] = __halves2half2(__float2half_rn(v.z), __float2half_rn(v.w));
        }
    } else {
        const float* A = (const float*)Av;
        for (int idx = tid; idx < 64 * 16; idx += 256) {
            int r = idx >> 4, k = idx & 15;
            int gr = rowBase + r;
            float a = (gr < M && k < IN_DIM) ? __ldg(A + (size_t)gr * IN_DIM + k) : 0.f;
            aS[r * APAD + k] = __float2half_rn(a);
        }
    }
    for (int idx = tid; idx < kmax1 * 16; idx += 256) {
        int k = idx >> 4, seg = idx & 15;
        *(uint4*)&wS[k * APAD + seg * 8] = __ldg((const uint4*)(W1 + k * HID) + seg);
    }
    __syncthreads();

    int warpR = (wid >> 2) << 5;
    int warpC = (wid & 3) << 5;
    uint32_t aBase = smem_u32(aS);
    uint32_t wBase = smem_u32(wS);
    float acc[2][4][4];

    #pragma unroll
    for (int m = 0; m < 2; m++)
        #pragma unroll
        for (int j = 0; j < 4; j++)
            #pragma unroll
            for (int q = 0; q < 4; q++) acc[m][j][q] = 0.f;

    // ================= pass 1 =================
    for (int s = 0; s < nsteps1; s++) {
        int k0 = s << 4;
        uint32_t aAddr = aBase +
            ((uint32_t)((warpR + (lane & 15)) * APAD + k0 + ((lane >> 4) << 3)) << 1);
        uint32_t a0[4], a1[4];
        LDSM_X4(a0[0], a0[1], a0[2], a0[3], aAddr);
        LDSM_X4(a1[0], a1[1], a1[2], a1[3], aAddr + 16 * APAD * 2);

        uint32_t bAddr = wBase +
            ((uint32_t)((k0 + (lane & 7) + ((lane >> 3) & 1) * 8) * APAD +
                        warpC + ((lane >> 4) << 3)) << 1);
        uint32_t bf[4][2];
        #pragma unroll
        for (int pp = 0; pp < 2; pp++) {
            uint32_t r0, r1, r2, r3;
            LDSM_X4T(r0, r1, r2, r3, bAddr + pp * 32);
            bf[2 * pp][0] = r0; bf[2 * pp][1] = r1;
            bf[2 * pp + 1][0] = r2; bf[2 * pp + 1][1] = r3;
        }
        #pragma unroll
        for (int j = 0; j < 4; j++) {
            mma_fp16(acc[0][j], a0, bf[j]);
            mma_fp16(acc[1][j], a1, bf[j]);
        }
    }
    __syncthreads();

    // ---- T1 = relu(acc + b1) -> fp16 into A region; load W2 ----
    #pragma unroll
    for (int m = 0; m < 2; m++) {
        #pragma unroll
        for (int j = 0; j < 4; j++) {
            #pragma unroll
            for (int q = 0; q < 4; q++) {
                int row = warpR + m * 16 + (lane >> 2) + ((q >> 1) << 3);
                int col = warpC + j * 8 + ((lane & 3) << 1) + (q & 1);
                float t = fmaxf(acc[m][j][q] + b1S[col], 0.f);
                aS[row * APAD + col] = __float2half_rn(t);
            }
        }
    }
    for (int idx = tid; idx < 128 * 16; idx += 256) {
        int k = idx >> 4, seg = idx & 15;
        *(uint4*)&wS[k * APAD + seg * 8] = __ldg((const uint4*)(W2 + k * HID) + seg);
    }
    __syncthreads();

    // ================= pass 2 (K = 128) =================
    #pragma unroll
    for (int m = 0; m < 2; m++)
        #pragma unroll
        for (int j = 0; j < 4; j++)
            #pragma unroll
            for (int q = 0; q < 4; q++) acc[m][j][q] = 0.f;

    for (int s = 0; s < 8; s++) {
        int k0 = s << 4;
        uint32_t aAddr = aBase +
            ((uint32_t)((warpR + (lane & 15)) * APAD + k0 + ((lane >> 4) << 3)) << 1);
        uint32_t a0[4], a1[4];
        LDSM_X4(a0[0], a0[1], a0[2], a0[3], aAddr);
        LDSM_X4(a1[0], a1[1], a1[2], a1[3], aAddr + 16 * APAD * 2);

        uint32_t bAddr = wBase +
            ((uint32_t)((k0 + (lane & 7) + ((lane >> 3) & 1) * 8) * APAD +
                        warpC + ((lane >> 4) << 3)) << 1);
        uint32_t bf[4][2];
        #pragma unroll
        for (int pp = 0; pp < 2; pp++) {
            uint32_t r0, r1, r2, r3;
            LDSM_X4T(r0, r1, r2, r3, bAddr + pp * 32);
            bf[2 * pp][0] = r0; bf[2 * pp][1] = r1;
            bf[2 * pp + 1][0] = r2; bf[2 * pp + 1][1] = r3;
        }
        #pragma unroll
        for (int j = 0; j < 4; j++) {
            mma_fp16(acc[0][j], a0, bf[j]);
            mma_fp16(acc[1][j], a1, bf[j]);
        }
    }
    __syncthreads();

    float* stg = (float*)smem;
    #pragma unroll
    for (int m = 0; m < 2; m++) {
        #pragma unroll
        for (int j = 0; j < 4; j++) {
            int row = warpR + m * 16 + (lane >> 2);
            int col = warpC + j * 8 + ((lane & 3) << 1);
            stg[row * STG_PITCH + col]       = acc[m][j][0];
            stg[row * STG_PITCH + col + 1]   = acc[m][j][1];
            stg[(row + 8) * STG_PITCH + col]     = acc[m][j][2];
            stg[(row + 8) * STG_PITCH + col + 1] = acc[m][j][3];
        }
    }
    __syncthreads();

    // ---- coalesced fp16 store + bias2/relu2 + fused BN stats (stats from fp32) ----
    {
        int c = tid & 127, hh = tid >> 7;
        float bia = b2S[c];
        float s0 = 0.f, q0 = 0.f;
        #pragma unroll 4
        for (int j = 0; j < 32; j++) {
            int r = hh * 32 + j;
            int gr = rowBase + r;
            if (gr < M) {
                float v = stg[r * STG_PITCH + c] + bia;
                if (do_relu2) v = fmaxf(v, 0.f);
                C[(size_t)gr * HID + c] = __float2half_rn(v);
                s0 += v;
                q0 += v * v;
            }
        }
        if (ssum) {
            statS[hh * 128 + c] = s0;
            statS[256 + hh * 128 + c] = q0;
            __syncthreads();
            if (tid < 128) {
                atomicAdd(&ssum[tid], statS[tid] + statS[128 + tid]);
                atomicAdd(&ssq[tid], statS[256 + tid] + statS[384 + tid]);
            }
        }
    }
}

// ======================= BN + relu + optional residual (fp16 in/out) =======================
__global__ void bn_relu_res_k(const uint2* __restrict__ tmp, const float* __restrict__ stats,
                              const float* __restrict__ gamma, const float* __restrict__ beta,
                              const uint2* __restrict__ res, uint2* __restrict__ out,
                              int n_rows) {
    size_t i = (size_t)blockIdx.x * blockDim.x + threadIdx.x;
    size_t total = (size_t)n_rows * 32;
    if (i >= total) return;
    int d = ((int)(i & 31)) << 2;
    float invN = 1.f / (float)n_rows;
    uint2 tv = tmp[i];
    float2 t01 = __half22float2(*(__half2*)&tv.x);
    float2 t23 = __half22float2(*(__half2*)&tv.y);
    float ox, oy, oz, ow;
    {
        float mu = stats[d] * invN;
        float var = stats[HID + d] * invN - mu * mu;
        ox = fmaxf((t01.x - mu) * rsqrtf(var + BN_EPS) * gamma[d] + beta[d], 0.f);
    }
    {
        float mu = stats[d + 1] * invN;
        float var = stats[HID + d + 1] * invN - mu * mu;
        oy = fmaxf((t01.y - mu) * rsqrtf(var + BN_EPS) * gamma[d + 1] + beta[d + 1], 0.f);
    }
    {
        float mu = stats[d + 2] * invN;
        float var = stats[HID + d + 2] * invN - mu * mu;
        oz = fmaxf((t23.x - mu) * rsqrtf(var + BN_EPS) * gamma[d + 2] + beta[d + 2], 0.f);
    }
    {
        float mu = stats[d + 3] * invN;
        float var = stats[HID + d + 3] * invN - mu * mu;
        ow = fmaxf((t23.y - mu) * rsqrtf(var + BN_EPS) * gamma[d + 3] + beta[d + 3], 0.f);
    }
    if (res) {
        uint2 rv = res[i];
        float2 r01 = __half22float2(*(__half2*)&rv.x);
        float2 r23 = __half22float2(*(__half2*)&rv.y);
        ox += r01.x; oy += r01.y; oz += r23.x; ow += r23.y;
    }
    __half2 o01 = __floats2half2_rn(ox, oy);
    __half2 o23 = __floats2half2_rn(oz, ow);
    uint2 ov;
    ov.x = *(uint32_t*)&o01;
    ov.y = *(uint32_t*)&o23;
    out[i] = ov;
}

// ======================= pooling =======================
__global__ void graph_ptr_k(const int* __restrict__ batch, int* __restrict__ gptr) {
    int g = blockIdx.x * blockDim.x + threadIdx.x;
    if (g > N_GRAPHS) return;
    int lo = 0, hi = N_NODES;
    while (lo < hi) {
        int mid = (lo + hi) >> 1;
        if (batch[mid] < g) lo = mid + 1; else hi = mid;
    }
    gptr[g] = lo;
}
__global__ void pool_k(const __half* __restrict__ h, const int* __restrict__ gptr,
                       float* __restrict__ pooled) {
    int g = blockIdx.x;
    int d = threadIdx.x;
    int a = gptr[g], b = gptr[g + 1];
    float acc = 0.f;
    for (int n = a; n < b; n++) acc += __half2float(h[(size_t)n * HID + d]);
    int cnt = b - a;
    float c = (float)(cnt > 1 ? cnt : 1);
    pooled[(size_t)g * HID + d] = acc / c;
}

// ======================= head final dot (fp16 z) =======================
__global__ void head_out_k(const __half* __restrict__ z, const float* __restrict__ w,
                           const float* __restrict__ b, float* __restrict__ out) {
    int g = blockIdx.x;
    int t = threadIdx.x; // 128
    float v = __half2float(z[(size_t)g * HID + t]) * w[t];
    #pragma unroll
    for (int off = 16; off; off >>= 1) v += __shfl_down_sync(0xFFFFFFFFu, v, off);
    __shared__ float s[4];
    if ((t & 31) == 0) s[t >> 5] = v;
    __syncthreads();
    if (t == 0) out[g] = s[0] + s[1] + s[2] + s[3] + b[0];
}

// ======================= host =======================
static void* sym_addr(const void* sym) {
    void* p = nullptr;
    cudaGetSymbolAddress(&p, sym);
    return p;
}

extern "C" void kernel_launch(void* const* d_in, const int* in_sizes, int n_in,
                              void* d_out, int out_size) {
    const float* x        = (const float*)d_in[0];
    const float* edge_attr= (const float*)d_in[1];
    const float* e_w0     = (const float*)d_in[2];
    const float* e_b0     = (const float*)d_in[3];
    const float* w1_0     = (const float*)d_in[4];
    const float* b1_0     = (const float*)d_in[5];
    const float* w2_0     = (const float*)d_in[6];
    const float* b2_0     = (const float*)d_in[7];
    const float* gamma0   = (const float*)d_in[8];
    const float* beta0    = (const float*)d_in[9];
    const float* eps0     = (const float*)d_in[10];
    const float* e_w      = (const float*)d_in[11];
    const float* e_b      = (const float*)d_in[12];
    const float* w1       = (const float*)d_in[13];
    const float* b1       = (const float*)d_in[14];
    const float* w2       = (const float*)d_in[15];
    const float* b2       = (const float*)d_in[16];
    const float* gamma    = (const float*)d_in[17];
    const float* beta     = (const float*)d_in[18];
    const float* eps_r    = (const float*)d_in[19];
    const float* hw1      = (const float*)d_in[20];
    const float* hb1      = (const float*)d_in[21];
    const float* hw2      = (const float*)d_in[22];
    const float* hb2      = (const float*)d_in[23];
    const float* hw3      = (const float*)d_in[24];
    const float* hb3      = (const float*)d_in[25];
    const int*   edge_index = (const int*)d_in[26];
    const int*   batch    = (const int*)d_in[27];

    const int* src = edge_index;
    const int* dst = edge_index + N_EDGES;

    float* pre11 = (float*)sym_addr(g_pre11);
    __half* preh = (__half*)sym_addr(g_preh);
    __half* tmp  = (__half*)sym_addr(g_tmp);
    __half* hA   = (__half*)sym_addr(g_hA);
    __half* hB   = (__half*)sym_addr(g_hB);
    int*   deg   = (int*)sym_addr(g_deg);
    int*   rowptr= (int*)sym_addr(g_rowptr);
    int*   cursor= (int*)sym_addr(g_cursor);
    int*   srcp  = (int*)sym_addr(g_srcp);
    uint2* eah   = (uint2*)sym_addr(g_eah);
    int*   gptr  = (int*)sym_addr(g_gptr);
    float* stats = (float*)sym_addr(g_stats);
    float* pool  = (float*)sym_addr(g_pool);
    __half* z2   = (__half*)sym_addr(g_z2);
    __half* wh   = (__half*)sym_addr(g_wh);
    float* out   = (float*)d_out;

    cudaFuncSetAttribute(gemm_mlp_k, cudaFuncAttributeMaxDynamicSharedMemorySize, SM_TOTAL);

    const int SLOT = 128 * 128;

    init_k<<<(12 * 16384 + 255) / 256, 256>>>(w1_0, w2_0, w1, w2, hw1, hw2, wh, deg, stats);
    count_deg_k<<<(N_EDGES + 255) / 256, 256>>>(dst, deg);
    scan_csr_k<<<1, 1024>>>(deg, rowptr, cursor);
    fill_csr_k<<<(N_EDGES + 255) / 256, 256>>>(src, dst, edge_attr, cursor, srcp, eah);

    const int GB_N = (N_NODES + 63) / 64;
    const int GB_G = (N_GRAPHS + 63) / 64;
    const int BN_BLOCKS = (int)(((size_t)N_NODES * 32 + 255) / 256);

    // ---- layer 0 ----
    aggregate11_k<<<(N_NODES + 3) / 4, 128>>>(x, eah, e_w0, e_b0, eps0, srcp, rowptr, pre11);
    gemm_mlp_k<<<GB_N, 256, SM_TOTAL>>>(pre11, N_NODES, 0,
                                        wh + 0 * SLOT, b1_0,
                                        wh + 1 * SLOT, b2_0,
                                        tmp, 0, stats, stats + HID, 1);
    bn_relu_res_k<<<BN_BLOCKS, 256>>>((const uint2*)tmp, stats, gamma0, beta0,
                                      nullptr, (uint2*)hA, N_NODES);

    // ---- layers 1..4 ----
    __half* cur = hA;
    __half* nxt = hB;
    for (int i = 0; i < N_REST; i++) {
        float* st = stats + (size_t)(1 + i) * 2 * HID;
        aggregate128_k<<<(N_NODES + 7) / 8, 256>>>((const uint2*)cur, eah,
                                                   e_w + (size_t)i * 3 * HID,
                                                   e_b + (size_t)i * HID, eps_r + i,
                                                   srcp, rowptr, (uint2*)preh);
        gemm_mlp_k<<<GB_N, 256, SM_TOTAL>>>(preh, N_NODES, 2,
                                            wh + (2 + i) * SLOT, b1 + (size_t)i * HID,
                                            wh + (6 + i) * SLOT, b2 + (size_t)i * HID,
                                            tmp, 0, st, st + HID, 8);
        bn_relu_res_k<<<BN_BLOCKS, 256>>>((const uint2*)tmp, st,
                                          gamma + (size_t)i * HID, beta + (size_t)i * HID,
                                          (const uint2*)cur, (uint2*)nxt, N_NODES);
        __half* t = cur; cur = nxt; nxt = t;
    }

    // ---- pooling ----
    graph_ptr_k<<<(N_GRAPHS + 1 + 127) / 128, 128>>>(batch, gptr);
    pool_k<<<N_GRAPHS, HID>>>(cur, gptr, pool);

    // ---- head ----
    gemm_mlp_k<<<GB_G, 256, SM_TOTAL>>>(pool, N_GRAPHS, 1,
                                        wh + 10 * SLOT, hb1,
                                        wh + 11 * SLOT, hb2,
                                        z2, 1, nullptr, nullptr, 8);
    head_out_k<<<N_GRAPHS, HID>>>(z2, hw3, hb3, out);
}

// round 17
// speedup vs baseline: 1.0897x; 1.0322x over previous
#include <cuda_runtime.h>
#include <cuda_fp16.h>
#include <cstdint>

#define N_NODES 100000
#define N_EDGES 600000
#define N_GRAPHS 5000
#define IN_DIM 11
#define HID 128
#define EDGE_DIM 3
#define N_REST 4
#define BN_EPS 1e-5f

// ======================= PTX helpers (baseline sm_80+ ISA only) =======================
__device__ __forceinline__ uint32_t smem_u32(const void* p) {
    uint32_t a;
    asm("{ .reg .u64 t; cvta.to.shared.u64 t, %1; cvt.u32.u64 %0, t; }" : "=r"(a) : "l"(p));
    return a;
}

#define LDSM_X4(r0, r1, r2, r3, addr)                                            \
    asm volatile("ldmatrix.sync.aligned.m8n8.x4.shared.b16 {%0,%1,%2,%3}, [%4];" \
                 : "=r"(r0), "=r"(r1), "=r"(r2), "=r"(r3) : "r"(addr))

#define LDSM_X4T(r0, r1, r2, r3, addr)                                                 \
    asm volatile("ldmatrix.sync.aligned.m8n8.x4.trans.shared.b16 {%0,%1,%2,%3}, [%4];" \
                 : "=r"(r0), "=r"(r1), "=r"(r2), "=r"(r3) : "r"(addr))

__device__ __forceinline__ void mma_fp16(float* c, const uint32_t* a, const uint32_t* b) {
    asm volatile(
        "mma.sync.aligned.m16n8k16.row.col.f32.f16.f16.f32 "
        "{%0,%1,%2,%3}, {%4,%5,%6,%7}, {%8,%9}, {%0,%1,%2,%3};"
        : "+f"(c[0]), "+f"(c[1]), "+f"(c[2]), "+f"(c[3])
        : "r"(a[0]), "r"(a[1]), "r"(a[2]), "r"(a[3]), "r"(b[0]), "r"(b[1]));
}

// ======================= scratch =======================
__device__ float  g_pre11[(size_t)N_NODES * IN_DIM];     // layer0 aggregate out (fp32)
__device__ __half g_preh[(size_t)N_NODES * HID];         // HID-layer aggregate out (fp16)
__device__ __half g_tmp[(size_t)N_NODES * HID];          // GEMM out pre-BN (fp16)
__device__ __half g_hA[(size_t)N_NODES * HID];           // h buffers (fp16)
__device__ __half g_hB[(size_t)N_NODES * HID];

__device__ int g_deg[N_NODES];
__device__ int g_rowptr[N_NODES + 1];
__device__ int g_cursor[N_NODES + 1];
__device__ int g_srcp[N_EDGES];                          // permuted src (separate dense stream)
__device__ float4 g_eap[N_EDGES];                        // permuted edge attrs fp32 (separate stream)
__device__ int g_gptr[N_GRAPHS + 1];

__device__ float g_stats[5 * 2 * HID];
__device__ float g_pool[(size_t)N_GRAPHS * HID];
__device__ __half g_z2[(size_t)N_GRAPHS * HID];

// pre-rounded fp16 weights: 12 slots of [128][128]
__device__ __half g_wh[12 * 128 * 128];

// ======================= init =======================
__global__ void init_k(const float* __restrict__ w1_0, const float* __restrict__ w2_0,
                       const float* __restrict__ w1, const float* __restrict__ w2,
                       const float* __restrict__ hw1, const float* __restrict__ hw2,
                       __half* __restrict__ wh,
                       int* __restrict__ deg, float* __restrict__ stats) {
    int idx = blockIdx.x * 256 + threadIdx.x;
    if (idx < N_NODES) deg[idx] = 0;
    if (idx < 5 * 2 * HID) stats[idx] = 0.f;
    if (idx >= 12 * 16384) return;
    int slot = idx >> 14, off = idx & 16383;
    int k = off >> 7;
    float v = 0.f;
    if (slot == 0) { if (k < IN_DIM) v = w1_0[off]; }
    else if (slot == 1) v = w2_0[off];
    else if (slot < 6) v = w1[(slot - 2) * 16384 + off];
    else if (slot < 10) v = w2[(slot - 6) * 16384 + off];
    else if (slot == 10) v = hw1[off];
    else v = hw2[off];
    wh[idx] = __float2half_rn(v);
}

// ======================= CSR build =======================
__global__ void count_deg_k(const int* __restrict__ dst, int* __restrict__ deg) {
    int e = blockIdx.x * blockDim.x + threadIdx.x;
    if (e < N_EDGES) atomicAdd(&deg[dst[e]], 1);
}

__global__ void scan_csr_k(const int* __restrict__ deg, int* __restrict__ rowptr,
                           int* __restrict__ cursor) {
    __shared__ int warpS[32];
    __shared__ int warpOff[32];
    __shared__ int carryS;
    int tid = threadIdx.x, lane = tid & 31, w = tid >> 5;
    if (tid == 0) { carryS = 0; rowptr[0] = 0; }
    __syncthreads();
    for (int base = 0; base < N_NODES; base += 1024) {
        int i = base + tid;
        int v = (i < N_NODES) ? deg[i] : 0;
        int x = v;
        #pragma unroll
        for (int o = 1; o < 32; o <<= 1) {
            int t = __shfl_up_sync(0xFFFFFFFFu, x, o);
            if (lane >= o) x += t;
        }
        if (lane == 31) warpS[w] = x;
        __syncthreads();
        if (w == 0) {
            int y = warpS[lane];
            int z = y;
            #pragma unroll
            for (int o = 1; o < 32; o <<= 1) {
                int t = __shfl_up_sync(0xFFFFFFFFu, z, o);
                if (lane >= o) z += t;
            }
            warpOff[lane] = z - y;
            if (lane == 31) warpS[0] = z;
        }
        __syncthreads();
        int c = carryS;
        int incl = x + warpOff[w];
        if (i < N_NODES) {
            rowptr[i + 1] = c + incl;
            cursor[i] = c + incl - v;
        }
        int chunkTot = warpS[0];
        __syncthreads();
        if (tid == 0) carryS = c + chunkTot;
        __syncthreads();
    }
}

__global__ void fill_csr_k(const int* __restrict__ src, const int* __restrict__ dst,
                           const float* __restrict__ ea, int* __restrict__ cursor,
                           int* __restrict__ srcp, float4* __restrict__ eap) {
    int e = blockIdx.x * blockDim.x + threadIdx.x;
    if (e < N_EDGES) {
        int p = atomicAdd(&cursor[dst[e]], 1);
        srcp[p] = src[e];
        float4 t;
        t.x = ea[(size_t)e * 3];
        t.y = ea[(size_t)e * 3 + 1];
        t.z = ea[(size_t)e * 3 + 2];
        t.w = 0.f;
        eap[p] = t;
    }
}

// ======================= aggregation =======================
__global__ void aggregate11_k(const float* __restrict__ h, const float4* __restrict__ eap,
                              const float* __restrict__ ew, const float* __restrict__ eb,
                              const float* __restrict__ epsp,
                              const int* __restrict__ srcp, const int* __restrict__ rowptr,
                              float* __restrict__ out) {
    int n = blockIdx.x * 4 + (threadIdx.x >> 5);
    int d = threadIdx.x & 31;
    if (n >= N_NODES || d >= IN_DIM) return;
    float w0 = ew[d], w1 = ew[IN_DIM + d], w2 = ew[2 * IN_DIM + d], b = eb[d];
    int s0 = rowptr[n], s1 = rowptr[n + 1];
    float acc = 0.f;
    int p = s0;
    for (; p + 2 <= s1; p += 2) {
        int i0 = srcp[p], i1 = srcp[p + 1];
        float4 e0 = eap[p], e1 = eap[p + 1];
        float gg0 = h[(size_t)i0 * IN_DIM + d];
        float gg1 = h[(size_t)i1 * IN_DIM + d];
        acc += fmaxf(gg0 + e0.x * w0 + e0.y * w1 + e0.z * w2 + b, 0.f);
        acc += fmaxf(gg1 + e1.x * w0 + e1.y * w1 + e1.z * w2 + b, 0.f);
    }
    for (; p < s1; p++) {
        int i0 = srcp[p];
        float4 e0 = eap[p];
        acc += fmaxf(h[(size_t)i0 * IN_DIM + d] + e0.x * w0 + e0.y * w1 + e0.z * w2 + b, 0.f);
    }
    float eps = *epsp;
    out[(size_t)n * IN_DIM + d] = (1.f + eps) * h[(size_t)n * IN_DIM + d] + acc;
}

// warp-per-node; h fp16 (row = 32 uint2); lane owns dims 4*lane..4*lane+3.
__global__ void __launch_bounds__(256)
aggregate128_k(const uint2* __restrict__ h2, const float4* __restrict__ eap,
               const float* __restrict__ ew, const float* __restrict__ eb,
               const float* __restrict__ epsp,
               const int* __restrict__ srcp, const int* __restrict__ rowptr,
               uint2* __restrict__ pre2) {
    int n = blockIdx.x * 8 + (threadIdx.x >> 5);
    int lane = threadIdx.x & 31;
    if (n >= N_NODES) return;
    float4 w0 = __ldg((const float4*)ew + lane);
    float4 w1 = __ldg((const float4*)(ew + HID) + lane);
    float4 w2 = __ldg((const float4*)(ew + 2 * HID) + lane);
    float4 bb = __ldg((const float4*)eb + lane);
    int s0 = rowptr[n], s1 = rowptr[n + 1];
    float ax = 0.f, ay = 0.f, az = 0.f, aw = 0.f;
    int p = s0;
    for (; p + 4 <= s1; p += 4) {
        int i0 = __ldg(srcp + p), i1 = __ldg(srcp + p + 1);
        int i2 = __ldg(srcp + p + 2), i3 = __ldg(srcp + p + 3);
        float4 e0 = __ldg(eap + p), e1 = __ldg(eap + p + 1);
        float4 e2 = __ldg(eap + p + 2), e3 = __ldg(eap + p + 3);
        uint2 r0 = __ldg(h2 + (size_t)i0 * 32 + lane);
        uint2 r1 = __ldg(h2 + (size_t)i1 * 32 + lane);
        uint2 r2 = __ldg(h2 + (size_t)i2 * 32 + lane);
        uint2 r3 = __ldg(h2 + (size_t)i3 * 32 + lane);
        float2 g01, g23;
        float c0, c1, c2, c3;
        g01 = __half22float2(*(__half2*)&r0.x);
        g23 = __half22float2(*(__half2*)&r0.y);
        c0 = e0.x * w0.x + e0.y * w1.x + e0.z * w2.x + bb.x;
        c1 = e0.x * w0.y + e0.y * w1.y + e0.z * w2.y + bb.y;
        c2 = e0.x * w0.z + e0.y * w1.z + e0.z * w2.z + bb.z;
        c3 = e0.x * w0.w + e0.y * w1.w + e0.z * w2.w + bb.w;
        ax += fmaxf(g01.x + c0, 0.f); ay += fmaxf(g01.y + c1, 0.f);
        az += fmaxf(g23.x + c2, 0.f); aw += fmaxf(g23.y + c3, 0.f);
        g01 = __half22float2(*(__half2*)&r1.x);
        g23 = __half22float2(*(__half2*)&r1.y);
        c0 = e1.x * w0.x + e1.y * w1.x + e1.z * w2.x + bb.x;
        c1 = e1.x * w0.y + e1.y * w1.y + e1.z * w2.y + bb.y;
        c2 = e1.x * w0.z + e1.y * w1.z + e1.z * w2.z + bb.z;
        c3 = e1.x * w0.w + e1.y * w1.w + e1.z * w2.w + bb.w;
        ax += fmaxf(g01.x + c0, 0.f); ay += fmaxf(g01.y + c1, 0.f);
        az += fmaxf(g23.x + c2, 0.f); aw += fmaxf(g23.y + c3, 0.f);
        g01 = __half22float2(*(__half2*)&r2.x);
        g23 = __half22float2(*(__half2*)&r2.y);
        c0 = e2.x * w0.x + e2.y * w1.x + e2.z * w2.x + bb.x;
        c1 = e2.x * w0.y + e2.y * w1.y + e2.z * w2.y + bb.y;
        c2 = e2.x * w0.z + e2.y * w1.z + e2.z * w2.z + bb.z;
        c3 = e2.x * w0.w + e2.y * w1.w + e2.z * w2.w + bb.w;
        ax += fmaxf(g01.x + c0, 0.f); ay += fmaxf(g01.y + c1, 0.f);
        az += fmaxf(g23.x + c2, 0.f); aw += fmaxf(g23.y + c3, 0.f);
        g01 = __half22float2(*(__half2*)&r3.x);
        g23 = __half22float2(*(__half2*)&r3.y);
        c0 = e3.x * w0.x + e3.y * w1.x + e3.z * w2.x + bb.x;
        c1 = e3.x * w0.y + e3.y * w1.y + e3.z * w2.y + bb.y;
        c2 = e3.x * w0.z + e3.y * w1.z + e3.z * w2.z + bb.z;
        c3 = e3.x * w0.w + e3.y * w1.w + e3.z * w2.w + bb.w;
        ax += fmaxf(g01.x + c0, 0.f); ay += fmaxf(g01.y + c1, 0.f);
        az += fmaxf(g23.x + c2, 0.f); aw += fmaxf(g23.y + c3, 0.f);
    }
    for (; p < s1; p++) {
        int i0 = __ldg(srcp + p);
        float4 e0 = __ldg(eap + p);
        uint2 r0 = __ldg(h2 + (size_t)i0 * 32 + lane);
        float2 g01 = __half22float2(*(__half2*)&r0.x);
        float2 g23 = __half22float2(*(__half2*)&r0.y);
        ax += fmaxf(g01.x + e0.x * w0.x + e0.y * w1.x + e0.z * w2.x + bb.x, 0.f);
        ay += fmaxf(g01.y + e0.x * w0.y + e0.y * w1.y + e0.z * w2.y + bb.y, 0.f);
        az += fmaxf(g23.x + e0.x * w0.z + e0.y * w1.z + e0.z * w2.z + bb.z, 0.f);
        aw += fmaxf(g23.y + e0.x * w0.w + e0.y * w1.w + e0.z * w2.w + bb.w, 0.f);
    }
    float eps1 = 1.f + *epsp;
    uint2 rn = __ldg(h2 + (size_t)n * 32 + lane);
    float2 hn01 = __half22float2(*(__half2*)&rn.x);
    float2 hn23 = __half22float2(*(__half2*)&rn.y);
    __half2 o01 = __floats2half2_rn(eps1 * hn01.x + ax, eps1 * hn01.y + ay);
    __half2 o23 = __floats2half2_rn(eps1 * hn23.x + az, eps1 * hn23.y + aw);
    uint2 ov;
    ov.x = *(uint32_t*)&o01;
    ov.y = *(uint32_t*)&o23;
    pre2[(size_t)n * 32 + lane] = ov;
}

// ======================= fused 2-GEMM MLP (pure fp16, M=64, 4 CTAs/SM) =======================
#define APAD 136
#define SX      0
#define SY      17408
#define S_B1    52224
#define S_B2    52736
#define S_STAT  53248
#define SM_TOTAL (S_STAT + 2048)
#define STG_PITCH 130

// a_mode: 0 = fp32 scalar (layer0, pitch IN_DIM), 1 = fp32 float4 (head), 2 = fp16 direct
__global__ void __launch_bounds__(256, 4)
gemm_mlp_k(const void* __restrict__ Av, int M, int a_mode,
           const __half* __restrict__ W1, const float* __restrict__ b1,
           const __half* __restrict__ W2, const float* __restrict__ b2,
           __half* __restrict__ C, int do_relu2,
           float* __restrict__ ssum, float* __restrict__ ssq, int nsteps1) {
    extern __shared__ __align__(16) char smem[];
    __half* aS = (__half*)(smem + SX);
    __half* wS = (__half*)(smem + SY);
    float* b1S = (float*)(smem + S_B1);
    float* b2S = (float*)(smem + S_B2);
    float* statS = (float*)(smem + S_STAT);

    int tid = threadIdx.x;
    int lane = tid & 31;
    int wid = tid >> 5;
    int rowBase = blockIdx.x * 64;
    int kmax1 = nsteps1 << 4;

    if (tid < HID) { b1S[tid] = b1[tid]; b2S[tid] = b2[tid]; }

    // ---- load A [64 x kmax1] ----
    if (a_mode == 2) {
        const __half* Ah = (const __half*)Av;
        const uint4 Z4 = make_uint4(0u, 0u, 0u, 0u);
        for (int idx = tid; idx < 64 * 16; idx += 256) {
            int r = idx >> 4, seg = idx & 15;
            int gr = rowBase + r;
            uint4 v = (gr < M) ? __ldg((const uint4*)(Ah + (size_t)gr * HID) + seg) : Z4;
            *(uint4*)&aS[r * APAD + seg * 8] = v;
        }
    } else if (a_mode == 1) {
        const float* A = (const float*)Av;
        for (int idx = tid; idx < 64 * 32; idx += 256) {
            int r = idx >> 5, seg = idx & 31;
            int gr = rowBase + r;
            float4 v = (gr < M) ? __ldg((const float4*)(A + (size_t)gr * HID) + seg)
                                : make_float4(0.f, 0.f, 0.f, 0.f);
            __half2* ph = (__half2*)&aS[r * APAD + seg * 4];
            ph[0] = __halves2half2(__float2half_rn(v.x), __float2half_rn(v.y));
            ph[1] = __halves2half2(__float2half_rn(v.z), __float2half_rn(v.w));
        }
    } else {
        const float* A = (const float*)Av;
        for (int idx = tid; idx < 64 * 16; idx += 256) {
            int r = idx >> 4, k = idx & 15;
            int gr = rowBase + r;
            float a = (gr < M && k < IN_DIM) ? __ldg(A + (size_t)gr * IN_DIM + k) : 0.f;
            aS[r * APAD + k] = __float2half_rn(a);
        }
    }
    for (int idx = tid; idx < kmax1 * 16; idx += 256) {
        int k = idx >> 4, seg = idx & 15;
        *(uint4*)&wS[k * APAD + seg * 8] = __ldg((const uint4*)(W1 + k * HID) + seg);
    }
    __syncthreads();

    int warpR = (wid >> 2) << 5;
    int warpC = (wid & 3) << 5;
    uint32_t aBase = smem_u32(aS);
    uint32_t wBase = smem_u32(wS);
    float acc[2][4][4];

    #pragma unroll
    for (int m = 0; m < 2; m++)
        #pragma unroll
        for (int j = 0; j < 4; j++)
            #pragma unroll
            for (int q = 0; q < 4; q++) acc[m][j][q] = 0.f;

    // ================= pass 1 =================
    for (int s = 0; s < nsteps1; s++) {
        int k0 = s << 4;
        uint32_t aAddr = aBase +
            ((uint32_t)((warpR + (lane & 15)) * APAD + k0 + ((lane >> 4) << 3)) << 1);
        uint32_t a0[4], a1[4];
        LDSM_X4(a0[0], a0[1], a0[2], a0[3], aAddr);
        LDSM_X4(a1[0], a1[1], a1[2], a1[3], aAddr + 16 * APAD * 2);

        uint32_t bAddr = wBase +
            ((uint32_t)((k0 + (lane & 7) + ((lane >> 3) & 1) * 8) * APAD +
                        warpC + ((lane >> 4) << 3)) << 1);
        uint32_t bf[4][2];
        #pragma unroll
        for (int pp = 0; pp < 2; pp++) {
            uint32_t r0, r1, r2, r3;
            LDSM_X4T(r0, r1, r2, r3, bAddr + pp * 32);
            bf[2 * pp][0] = r0; bf[2 * pp][1] = r1;
            bf[2 * pp + 1][0] = r2; bf[2 * pp + 1][1] = r3;
        }
        #pragma unroll
        for (int j = 0; j < 4; j++) {
            mma_fp16(acc[0][j], a0, bf[j]);
            mma_fp16(acc[1][j], a1, bf[j]);
        }
    }
    __syncthreads();

    // ---- T1 = relu(acc + b1) -> fp16 into A region; load W2 ----
    #pragma unroll
    for (int m = 0; m < 2; m++) {
        #pragma unroll
        for (int j = 0; j < 4; j++) {
            #pragma unroll
            for (int q = 0; q < 4; q++) {
                int row = warpR + m * 16 + (lane >> 2) + ((q >> 1) << 3);
                int col = warpC + j * 8 + ((lane & 3) << 1) + (q & 1);
                float t = fmaxf(acc[m][j][q] + b1S[col], 0.f);
                aS[row * APAD + col] = __float2half_rn(t);
            }
        }
    }
    for (int idx = tid; idx < 128 * 16; idx += 256) {
        int k = idx >> 4, seg = idx & 15;
        *(uint4*)&wS[k * APAD + seg * 8] = __ldg((const uint4*)(W2 + k * HID) + seg);
    }
    __syncthreads();

    // ================= pass 2 (K = 128) =================
    #pragma unroll
    for (int m = 0; m < 2; m++)
        #pragma unroll
        for (int j = 0; j < 4; j++)
            #pragma unroll
            for (int q = 0; q < 4; q++) acc[m][j][q] = 0.f;

    for (int s = 0; s < 8; s++) {
        int k0 = s << 4;
        uint32_t aAddr = aBase +
            ((uint32_t)((warpR + (lane & 15)) * APAD + k0 + ((lane >> 4) << 3)) << 1);
        uint32_t a0[4], a1[4];
        LDSM_X4(a0[0], a0[1], a0[2], a0[3], aAddr);
        LDSM_X4(a1[0], a1[1], a1[2], a1[3], aAddr + 16 * APAD * 2);

        uint32_t bAddr = wBase +
            ((uint32_t)((k0 + (lane & 7) + ((lane >> 3) & 1) * 8) * APAD +
                        warpC + ((lane >> 4) << 3)) << 1);
        uint32_t bf[4][2];
        #pragma unroll
        for (int pp = 0; pp < 2; pp++) {
            uint32_t r0, r1, r2, r3;
            LDSM_X4T(r0, r1, r2, r3, bAddr + pp * 32);
            bf[2 * pp][0] = r0; bf[2 * pp][1] = r1;
            bf[2 * pp + 1][0] = r2; bf[2 * pp + 1][1] = r3;
        }
        #pragma unroll
        for (int j = 0; j < 4; j++) {
            mma_fp16(acc[0][j], a0, bf[j]);
            mma_fp16(acc[1][j], a1, bf[j]);
        }
    }
    __syncthreads();

    float* stg = (float*)smem;
    #pragma unroll
    for (int m = 0; m < 2; m++) {
        #pragma unroll
        for (int j = 0; j < 4; j++) {
            int row = warpR + m * 16 + (lane >> 2);
            int col = warpC + j * 8 + ((lane & 3) << 1);
            stg[row * STG_PITCH + col]       = acc[m][j][0];
            stg[row * STG_PITCH + col + 1]   = acc[m][j][1];
            stg[(row + 8) * STG_PITCH + col]     = acc[m][j][2];
            stg[(row + 8) * STG_PITCH + col + 1] = acc[m][j][3];
        }
    }
    __syncthreads();

    // ---- coalesced fp16 store + bias2/relu2 + fused BN stats (stats from fp32) ----
    {
        int c = tid & 127, hh = tid >> 7;
        float bia = b2S[c];
        float s0 = 0.f, q0 = 0.f;
        #pragma unroll 4
        for (int j = 0; j < 32; j++) {
            int r = hh * 32 + j;
            int gr = rowBase + r;
            if (gr < M) {
                float v = stg[r * STG_PITCH + c] + bia;
                if (do_relu2) v = fmaxf(v, 0.f);
                C[(size_t)gr * HID + c] = __float2half_rn(v);
                s0 += v;
                q0 += v * v;
            }
        }
        if (ssum) {
            statS[hh * 128 + c] = s0;
            statS[256 + hh * 128 + c] = q0;
            __syncthreads();
            if (tid < 128) {
                atomicAdd(&ssum[tid], statS[tid] + statS[128 + tid]);
                atomicAdd(&ssq[tid], statS[256 + tid] + statS[384 + tid]);
            }
        }
    }
}

// ======================= BN + relu + optional residual (fp16, uint4 ILP x2) =======================
__global__ void bn_relu_res_k(const uint4* __restrict__ tmp, const float* __restrict__ stats,
                              const float* __restrict__ gamma, const float* __restrict__ beta,
                              const uint4* __restrict__ res, uint4* __restrict__ out,
                              int n_rows) {
    size_t i = (size_t)blockIdx.x * blockDim.x + threadIdx.x;
    size_t total = (size_t)n_rows * 16;    // 8 halves per thread
    if (i >= total) return;
    int d = ((int)(i & 15)) << 3;
    float invN = 1.f / (float)n_rows;
    uint4 tv = tmp[i];
    float2 t01 = __half22float2(*(__half2*)&tv.x);
    float2 t23 = __half22float2(*(__half2*)&tv.y);
    float2 t45 = __half22float2(*(__half2*)&tv.z);
    float2 t67 = __half22float2(*(__half2*)&tv.w);
    float o[8];
    float tin[8] = {t01.x, t01.y, t23.x, t23.y, t45.x, t45.y, t67.x, t67.y};
    #pragma unroll
    for (int q = 0; q < 8; q++) {
        float mu = stats[d + q] * invN;
        float var = stats[HID + d + q] * invN - mu * mu;
        o[q] = fmaxf((tin[q] - mu) * rsqrtf(var + BN_EPS) * gamma[d + q] + beta[d + q], 0.f);
    }
    if (res) {
        uint4 rv = res[i];
        float2 r01 = __half22float2(*(__half2*)&rv.x);
        float2 r23 = __half22float2(*(__half2*)&rv.y);
        float2 r45 = __half22float2(*(__half2*)&rv.z);
        float2 r67 = __half22float2(*(__half2*)&rv.w);
        o[0] += r01.x; o[1] += r01.y; o[2] += r23.x; o[3] += r23.y;
        o[4] += r45.x; o[5] += r45.y; o[6] += r67.x; o[7] += r67.y;
    }
    __half2 o01 = __floats2half2_rn(o[0], o[1]);
    __half2 o23 = __floats2half2_rn(o[2], o[3]);
    __half2 o45 = __floats2half2_rn(o[4], o[5]);
    __half2 o67 = __floats2half2_rn(o[6], o[7]);
    uint4 ov;
    ov.x = *(uint32_t*)&o01;
    ov.y = *(uint32_t*)&o23;
    ov.z = *(uint32_t*)&o45;
    ov.w = *(uint32_t*)&o67;
    out[i] = ov;
}

// ======================= pooling =======================
__global__ void graph_ptr_k(const int* __restrict__ batch, int* __restrict__ gptr) {
    int g = blockIdx.x * blockDim.x + threadIdx.x;
    if (g > N_GRAPHS) return;
    int lo = 0, hi = N_NODES;
    while (lo < hi) {
        int mid = (lo + hi) >> 1;
        if (batch[mid] < g) lo = mid + 1; else hi = mid;
    }
    gptr[g] = lo;
}
__global__ void pool_k(const __half* __restrict__ h, const int* __restrict__ gptr,
                       float* __restrict__ pooled) {
    int g = blockIdx.x;
    int d = threadIdx.x;
    int a = gptr[g], b = gptr[g + 1];
    float acc = 0.f;
    for (int n = a; n < b; n++) acc += __half2float(h[(size_t)n * HID + d]);
    int cnt = b - a;
    float c = (float)(cnt > 1 ? cnt : 1);
    pooled[(size_t)g * HID + d] = acc / c;
}

// ======================= head final dot (fp16 z) =======================
__global__ void head_out_k(const __half* __restrict__ z, const float* __restrict__ w,
                           const float* __restrict__ b, float* __restrict__ out) {
    int g = blockIdx.x;
    int t = threadIdx.x; // 128
    float v = __half2float(z[(size_t)g * HID + t]) * w[t];
    #pragma unroll
    for (int off = 16; off; off >>= 1) v += __shfl_down_sync(0xFFFFFFFFu, v, off);
    __shared__ float s[4];
    if ((t & 31) == 0) s[t >> 5] = v;
    __syncthreads();
    if (t == 0) out[g] = s[0] + s[1] + s[2] + s[3] + b[0];
}

// ======================= host =======================
static void* sym_addr(const void* sym) {
    void* p = nullptr;
    cudaGetSymbolAddress(&p, sym);
    return p;
}

extern "C" void kernel_launch(void* const* d_in, const int* in_sizes, int n_in,
                              void* d_out, int out_size) {
    const float* x        = (const float*)d_in[0];
    const float* edge_attr= (const float*)d_in[1];
    const float* e_w0     = (const float*)d_in[2];
    const float* e_b0     = (const float*)d_in[3];
    const float* w1_0     = (const float*)d_in[4];
    const float* b1_0     = (const float*)d_in[5];
    const float* w2_0     = (const float*)d_in[6];
    const float* b2_0     = (const float*)d_in[7];
    const float* gamma0   = (const float*)d_in[8];
    const float* beta0    = (const float*)d_in[9];
    const float* eps0     = (const float*)d_in[10];
    const float* e_w      = (const float*)d_in[11];
    const float* e_b      = (const float*)d_in[12];
    const float* w1       = (const float*)d_in[13];
    const float* b1       = (const float*)d_in[14];
    const float* w2       = (const float*)d_in[15];
    const float* b2       = (const float*)d_in[16];
    const float* gamma    = (const float*)d_in[17];
    const float* beta     = (const float*)d_in[18];
    const float* eps_r    = (const float*)d_in[19];
    const float* hw1      = (const float*)d_in[20];
    const float* hb1      = (const float*)d_in[21];
    const float* hw2      = (const float*)d_in[22];
    const float* hb2      = (const float*)d_in[23];
    const float* hw3      = (const float*)d_in[24];
    const float* hb3      = (const float*)d_in[25];
    const int*   edge_index = (const int*)d_in[26];
    const int*   batch    = (const int*)d_in[27];

    const int* src = edge_index;
    const int* dst = edge_index + N_EDGES;

    float* pre11 = (float*)sym_addr(g_pre11);
    __half* preh = (__half*)sym_addr(g_preh);
    __half* tmp  = (__half*)sym_addr(g_tmp);
    __half* hA   = (__half*)sym_addr(g_hA);
    __half* hB   = (__half*)sym_addr(g_hB);
    int*   deg   = (int*)sym_addr(g_deg);
    int*   rowptr= (int*)sym_addr(g_rowptr);
    int*   cursor= (int*)sym_addr(g_cursor);
    int*   srcp  = (int*)sym_addr(g_srcp);
    float4* eap  = (float4*)sym_addr(g_eap);
    int*   gptr  = (int*)sym_addr(g_gptr);
    float* stats = (float*)sym_addr(g_stats);
    float* pool  = (float*)sym_addr(g_pool);
    __half* z2   = (__half*)sym_addr(g_z2);
    __half* wh   = (__half*)sym_addr(g_wh);
    float* out   = (float*)d_out;

    cudaFuncSetAttribute(gemm_mlp_k, cudaFuncAttributeMaxDynamicSharedMemorySize, SM_TOTAL);

    const int SLOT = 128 * 128;

    init_k<<<(12 * 16384 + 255) / 256, 256>>>(w1_0, w2_0, w1, w2, hw1, hw2, wh, deg, stats);
    count_deg_k<<<(N_EDGES + 255) / 256, 256>>>(dst, deg);
    scan_csr_k<<<1, 1024>>>(deg, rowptr, cursor);
    fill_csr_k<<<(N_EDGES + 255) / 256, 256>>>(src, dst, edge_attr, cursor, srcp, eap);

    const int GB_N = (N_NODES + 63) / 64;
    const int GB_G = (N_GRAPHS + 63) / 64;
    const int BN_BLOCKS = (int)(((size_t)N_NODES * 16 + 255) / 256);

    // ---- layer 0 ----
    aggregate11_k<<<(N_NODES + 3) / 4, 128>>>(x, eap, e_w0, e_b0, eps0, srcp, rowptr, pre11);
    gemm_mlp_k<<<GB_N, 256, SM_TOTAL>>>(pre11, N_NODES, 0,
                                        wh + 0 * SLOT, b1_0,
                                        wh + 1 * SLOT, b2_0,
                                        tmp, 0, stats, stats + HID, 1);
    bn_relu_res_k<<<BN_BLOCKS, 256>>>((const uint4*)tmp, stats, gamma0, beta0,
                                      nullptr, (uint4*)hA, N_NODES);

    // ---- layers 1..4 ----
    __half* cur = hA;
    __half* nxt = hB;
    for (int i = 0; i < N_REST; i++) {
        float* st = stats + (size_t)(1 + i) * 2 * HID;
        aggregate128_k<<<(N_NODES + 7) / 8, 256>>>((const uint2*)cur, eap,
                                                   e_w + (size_t)i * 3 * HID,
                                                   e_b + (size_t)i * HID, eps_r + i,
                                                   srcp, rowptr, (uint2*)preh);
        gemm_mlp_k<<<GB_N, 256, SM_TOTAL>>>(preh, N_NODES, 2,
                                            wh + (2 + i) * SLOT, b1 + (size_t)i * HID,
                                            wh + (6 + i) * SLOT, b2 + (size_t)i * HID,
                                            tmp, 0, st, st + HID, 8);
        bn_relu_res_k<<<BN_BLOCKS, 256>>>((const uint4*)tmp, st,
                                          gamma + (size_t)i * HID, beta + (size_t)i * HID,
                                          (const uint4*)cur, (uint4*)nxt, N_NODES);
        __half* t = cur; cur = nxt; nxt = t;
    }

    // ---- pooling ----
    graph_ptr_k<<<(N_GRAPHS + 1 + 127) / 128, 128>>>(batch, gptr);
    pool_k<<<N_GRAPHS, HID>>>(cur, gptr, pool);

    // ---- head ----
    gemm_mlp_k<<<GB_G, 256, SM_TOTAL>>>(pool, N_GRAPHS, 1,
                                        wh + 10 * SLOT, hb1,
                                        wh + 11 * SLOT, hb2,
                                        z2, 1, nullptr, nullptr, 8);
    head_out_k<<<N_GRAPHS, HID>>>(z2, hw3, hb3, out);
}